// round 1
// baseline (speedup 1.0000x reference)
#include <cuda_runtime.h>
#include <math.h>
#include <stdint.h>

#define D_IN       4096
#define NUM_HEADS  32
#define HEAD_DIM   128
#define NUM_KV     8
#define GROUP      4
#define SEQ        2048

// -------- scratch (device globals; no allocation allowed) --------
__device__ float g_q[(size_t)SEQ * NUM_HEADS * HEAD_DIM];   // 32 MB
__device__ float g_k[(size_t)SEQ * NUM_KV   * HEAD_DIM];    //  8 MB
__device__ float g_v[(size_t)SEQ * NUM_KV   * HEAD_DIM];    //  8 MB
__device__ float g_ctx[(size_t)SEQ * NUM_HEADS * HEAD_DIM]; // 32 MB

// =================================================================
// GEMM: C[M,N] = A[M,K] @ B[K,N], fp32. BM=BN=128, BK=16,
// 256 threads, 8x8 per-thread microtile.
// =================================================================
__global__ __launch_bounds__(256) void gemm128_kernel(
    const float* __restrict__ A, const float* __restrict__ B,
    float* __restrict__ C, int M, int N, int K)
{
    __shared__ float As[16][128];   // transposed: As[k][m]
    __shared__ float Bs[16][128];   // natural:   Bs[k][n]
    const int tid = threadIdx.x;
    const int tx = tid & 15;
    const int ty = tid >> 4;
    const int m0 = blockIdx.y * 128;
    const int n0 = blockIdx.x * 128;

    float acc[8][8];
#pragma unroll
    for (int i = 0; i < 8; ++i)
#pragma unroll
        for (int j = 0; j < 8; ++j) acc[i][j] = 0.f;

    for (int k0 = 0; k0 < K; k0 += 16) {
#pragma unroll
        for (int it = 0; it < 2; ++it) {
            int id  = tid + it * 256;      // 0..511
            int row = id >> 2;             // 0..127
            int kq  = id & 3;              // 0..3
            float4 a = *(const float4*)&A[(size_t)(m0 + row) * K + k0 + kq * 4];
            As[kq * 4 + 0][row] = a.x;
            As[kq * 4 + 1][row] = a.y;
            As[kq * 4 + 2][row] = a.z;
            As[kq * 4 + 3][row] = a.w;
        }
#pragma unroll
        for (int it = 0; it < 2; ++it) {
            int id = tid + it * 256;
            int kr = id >> 5;              // 0..15
            int nq = id & 31;              // 0..31
            *(float4*)&Bs[kr][nq * 4] =
                *(const float4*)&B[(size_t)(k0 + kr) * N + n0 + nq * 4];
        }
        __syncthreads();
#pragma unroll
        for (int k = 0; k < 16; ++k) {
            float4 a0 = *(const float4*)&As[k][ty * 8];
            float4 a1 = *(const float4*)&As[k][ty * 8 + 4];
            float4 b0 = *(const float4*)&Bs[k][tx * 8];
            float4 b1 = *(const float4*)&Bs[k][tx * 8 + 4];
            float a[8] = {a0.x, a0.y, a0.z, a0.w, a1.x, a1.y, a1.z, a1.w};
            float b[8] = {b0.x, b0.y, b0.z, b0.w, b1.x, b1.y, b1.z, b1.w};
#pragma unroll
            for (int i = 0; i < 8; ++i)
#pragma unroll
                for (int j = 0; j < 8; ++j)
                    acc[i][j] = fmaf(a[i], b[j], acc[i][j]);
        }
        __syncthreads();
    }
#pragma unroll
    for (int i = 0; i < 8; ++i) {
#pragma unroll
        for (int j = 0; j < 8; j += 4) {
            float4 v = make_float4(acc[i][j], acc[i][j+1], acc[i][j+2], acc[i][j+3]);
            *(float4*)&C[(size_t)(m0 + ty * 8 + i) * N + n0 + tx * 8 + j] = v;
        }
    }
}

// =================================================================
// Fused QK-RMSNorm + RoPE. One block per token; cos/sin computed
// once per token (double-precision angle + range reduction, then
// fp32 sincos), then applied to 32 Q heads + 8 K heads.
// =================================================================
__global__ __launch_bounds__(128) void norm_rope_kernel(
    float* __restrict__ q, float* __restrict__ k,
    const float* __restrict__ q_scale, const float* __restrict__ k_scale,
    const int* __restrict__ positions)
{
    const int n = blockIdx.x;
    const int d = threadIdx.x;  // 0..127
    __shared__ float cs[128], sn[128], buf[128], wred[4];

    if (d < 64) {
        // inv_freq = 10000^(-d/64) = 2^(-d * log2(1e4)/64)
        double invf = exp2(-(double)d * (13.287712379549449 / 64.0));
        double ang  = (double)positions[n] * invf;
        const double twopi = 6.283185307179586476925287;
        ang -= twopi * floor(ang / twopi);
        float af = (float)ang;
        float c, s;
        sincosf(af, &s, &c);
        cs[d] = c;       sn[d] = s;
        cs[d + 64] = c;  sn[d + 64] = s;
    }
    __syncthreads();

    const int nh = NUM_HEADS + NUM_KV;
    for (int h = 0; h < nh; ++h) {
        float* vec;
        const float* sc;
        if (h < NUM_HEADS) {
            vec = q + ((size_t)n * NUM_HEADS + h) * HEAD_DIM;
            sc = q_scale;
        } else {
            vec = k + ((size_t)n * NUM_KV + (h - NUM_HEADS)) * HEAD_DIM;
            sc = k_scale;
        }
        float val = vec[d];
        float ss = val * val;
#pragma unroll
        for (int o = 16; o > 0; o >>= 1) ss += __shfl_xor_sync(0xffffffffu, ss, o);
        if ((d & 31) == 0) wred[d >> 5] = ss;
        __syncthreads();
        float tot  = wred[0] + wred[1] + wred[2] + wred[3];
        float rinv = rsqrtf(tot * (1.0f / HEAD_DIM) + 1e-6f);
        float nv   = val * rinv * sc[d];
        buf[d] = nv;
        __syncthreads();
        float rot = (d < 64) ? -buf[d + 64] : buf[d - 64];
        vec[d] = fmaf(nv, cs[d], rot * sn[d]);
        __syncthreads();
    }
}

// =================================================================
// Flash attention (causal, GQA 4:1). BM=BN=64, 256 threads.
// Q,K,V tiles in smem (padded stride 129 -> scalar LDS, low
// conflicts); P staged transposed (stride 65); K/V share a buffer.
// Online softmax with per-row m/l in smem.
// =================================================================
#define FB_M 64
#define FB_N 64
#define QSTRIDE 129
#define PSTRIDE 65

__global__ __launch_bounds__(256) void flash_kernel(
    const float* __restrict__ Q, const float* __restrict__ Kg,
    const float* __restrict__ Vg, float* __restrict__ Og)
{
    extern __shared__ float sm[];
    float* Qs    = sm;                        // 64*129
    float* KVs   = Qs  + FB_M * QSTRIDE;      // 64*129 (K, then V)
    float* PsT   = KVs + FB_N * QSTRIDE;      // 64*65  (P transposed [j][i])
    float* red   = PsT + FB_N * PSTRIDE;      // 64*16
    float* row_m = red + FB_M * 16;           // 64
    float* row_l = row_m + FB_M;              // 64
    float* row_a = row_l + FB_M;              // 64

    const int tid = threadIdx.x;
    const int h   = blockIdx.y;
    const int kvh = h >> 2;                   // GROUP = 4
    const int mt  = blockIdx.x;
    const int m0  = mt * FB_M;
    const int sy  = tid >> 4;
    const int sx  = tid & 15;
    const int i0  = sy * 4;
    const int j0  = sx * 4;
    const int dd0 = sx * 8;
    const float softscale = 0.08838834764831845f;  // 1/sqrt(128)

    // ---- load Q tile (64 x 128), coalesced, scalar smem stores ----
#pragma unroll
    for (int it = 0; it < 8; ++it) {
        int id  = tid + it * 256;
        int tok = id >> 5;
        int d4  = id & 31;
        float4 v = *(const float4*)&Q[((size_t)(m0 + tok) * NUM_HEADS + h) * HEAD_DIM + d4 * 4];
        float* dst = &Qs[tok * QSTRIDE + d4 * 4];
        dst[0] = v.x; dst[1] = v.y; dst[2] = v.z; dst[3] = v.w;
    }
    if (tid < FB_M) { row_m[tid] = -1e30f; row_l[tid] = 0.f; }

    float o[4][8];
#pragma unroll
    for (int r = 0; r < 4; ++r)
#pragma unroll
        for (int e = 0; e < 8; ++e) o[r][e] = 0.f;

    for (int nt = 0; nt <= mt; ++nt) {
        const int n0 = nt * FB_N;
        __syncthreads();  // prev PV reads of KVs/PsT done
        // ---- load K tile ----
#pragma unroll
        for (int it = 0; it < 8; ++it) {
            int id  = tid + it * 256;
            int tok = id >> 5;
            int d4  = id & 31;
            float4 v = *(const float4*)&Kg[((size_t)(n0 + tok) * NUM_KV + kvh) * HEAD_DIM + d4 * 4];
            float* dst = &KVs[tok * QSTRIDE + d4 * 4];
            dst[0] = v.x; dst[1] = v.y; dst[2] = v.z; dst[3] = v.w;
        }
        __syncthreads();

        // ---- S = Q K^T (4x4 microtile) ----
        float s[4][4];
#pragma unroll
        for (int r = 0; r < 4; ++r)
#pragma unroll
            for (int c = 0; c < 4; ++c) s[r][c] = 0.f;

#pragma unroll 4
        for (int d = 0; d < HEAD_DIM; ++d) {
            float a0 = Qs[(i0 + 0) * QSTRIDE + d];
            float a1 = Qs[(i0 + 1) * QSTRIDE + d];
            float a2 = Qs[(i0 + 2) * QSTRIDE + d];
            float a3 = Qs[(i0 + 3) * QSTRIDE + d];
            float b0 = KVs[(j0 + 0) * QSTRIDE + d];
            float b1 = KVs[(j0 + 1) * QSTRIDE + d];
            float b2 = KVs[(j0 + 2) * QSTRIDE + d];
            float b3 = KVs[(j0 + 3) * QSTRIDE + d];
            s[0][0] = fmaf(a0, b0, s[0][0]); s[0][1] = fmaf(a0, b1, s[0][1]);
            s[0][2] = fmaf(a0, b2, s[0][2]); s[0][3] = fmaf(a0, b3, s[0][3]);
            s[1][0] = fmaf(a1, b0, s[1][0]); s[1][1] = fmaf(a1, b1, s[1][1]);
            s[1][2] = fmaf(a1, b2, s[1][2]); s[1][3] = fmaf(a1, b3, s[1][3]);
            s[2][0] = fmaf(a2, b0, s[2][0]); s[2][1] = fmaf(a2, b1, s[2][1]);
            s[2][2] = fmaf(a2, b2, s[2][2]); s[2][3] = fmaf(a2, b3, s[2][3]);
            s[3][0] = fmaf(a3, b0, s[3][0]); s[3][1] = fmaf(a3, b1, s[3][1]);
            s[3][2] = fmaf(a3, b2, s[3][2]); s[3][3] = fmaf(a3, b3, s[3][3]);
        }

        // ---- scale, causal mask, local row max ----
        const bool diag = (nt == mt);
#pragma unroll
        for (int r = 0; r < 4; ++r) {
            float lm = -1e30f;
#pragma unroll
            for (int c = 0; c < 4; ++c) {
                float v = s[r][c] * softscale;
                if (diag && (j0 + c > i0 + r)) v = -1e30f;
                s[r][c] = v;
                lm = fmaxf(lm, v);
            }
            red[(i0 + r) * 16 + sx] = lm;
        }
        __syncthreads();
        if (tid < FB_M) {
            float mold = row_m[tid];
            float mx   = mold;
#pragma unroll
            for (int t = 0; t < 16; ++t) mx = fmaxf(mx, red[tid * 16 + t]);
            row_m[tid] = mx;
            float alpha = __expf(mold - mx);  // first iter: exp(-1e30)=0
            row_a[tid]  = alpha;
            row_l[tid] *= alpha;
        }
        __syncthreads();

        // ---- P = exp(S - m), write P^T, partial row sums ----
#pragma unroll
        for (int r = 0; r < 4; ++r) {
            float mrow = row_m[i0 + r];
            float lsum = 0.f;
#pragma unroll
            for (int c = 0; c < 4; ++c) {
                float p = __expf(s[r][c] - mrow);
                PsT[(j0 + c) * PSTRIDE + (i0 + r)] = p;
                lsum += p;
            }
            red[(i0 + r) * 16 + sx] = lsum;
        }
        __syncthreads();
        if (tid < FB_M) {
            float t = 0.f;
#pragma unroll
            for (int q2 = 0; q2 < 16; ++q2) t += red[tid * 16 + q2];
            row_l[tid] += t;
        }
        // rescale O by alpha (row_a written before last sync)
        {
            float al[4];
#pragma unroll
            for (int r = 0; r < 4; ++r) al[r] = row_a[i0 + r];
#pragma unroll
            for (int r = 0; r < 4; ++r)
#pragma unroll
                for (int e = 0; e < 8; ++e) o[r][e] *= al[r];
        }
        __syncthreads();

        // ---- load V tile (overwrites K buffer) ----
#pragma unroll
        for (int it = 0; it < 8; ++it) {
            int id  = tid + it * 256;
            int tok = id >> 5;
            int d4  = id & 31;
            float4 v = *(const float4*)&Vg[((size_t)(n0 + tok) * NUM_KV + kvh) * HEAD_DIM + d4 * 4];
            float* dst = &KVs[tok * QSTRIDE + d4 * 4];
            dst[0] = v.x; dst[1] = v.y; dst[2] = v.z; dst[3] = v.w;
        }
        __syncthreads();

        // ---- O += P V ----
#pragma unroll 4
        for (int j = 0; j < FB_N; ++j) {
            float a0 = PsT[j * PSTRIDE + i0 + 0];
            float a1 = PsT[j * PSTRIDE + i0 + 1];
            float a2 = PsT[j * PSTRIDE + i0 + 2];
            float a3 = PsT[j * PSTRIDE + i0 + 3];
#pragma unroll
            for (int e = 0; e < 8; ++e) {
                float bv = KVs[j * QSTRIDE + dd0 + e];
                o[0][e] = fmaf(a0, bv, o[0][e]);
                o[1][e] = fmaf(a1, bv, o[1][e]);
                o[2][e] = fmaf(a2, bv, o[2][e]);
                o[3][e] = fmaf(a3, bv, o[3][e]);
            }
        }
    }

    // ---- finalize: O /= l, write out ----
    float linv[4];
#pragma unroll
    for (int r = 0; r < 4; ++r) linv[r] = 1.f / row_l[i0 + r];
#pragma unroll
    for (int r = 0; r < 4; ++r) {
        float4 v0 = make_float4(o[r][0] * linv[r], o[r][1] * linv[r],
                                o[r][2] * linv[r], o[r][3] * linv[r]);
        float4 v1 = make_float4(o[r][4] * linv[r], o[r][5] * linv[r],
                                o[r][6] * linv[r], o[r][7] * linv[r]);
        float* dst = &Og[((size_t)(m0 + i0 + r) * NUM_HEADS + h) * HEAD_DIM + dd0];
        *(float4*)dst       = v0;
        *(float4*)(dst + 4) = v1;
    }
}

// =================================================================
// kernel_launch
// =================================================================
extern "C" void kernel_launch(void* const* d_in, const int* in_sizes, int n_in,
                              void* d_out, int out_size)
{
    const float* x   = (const float*)d_in[0];
    const int*   pos = (const int*)  d_in[1];
    const float* Wq  = (const float*)d_in[2];
    const float* Wk  = (const float*)d_in[3];
    const float* Wv  = (const float*)d_in[4];
    const float* Wo  = (const float*)d_in[5];
    const float* qsc = (const float*)d_in[6];
    const float* ksc = (const float*)d_in[7];
    float* out = (float*)d_out;

    float *gq, *gk, *gv, *gctx;
    cudaGetSymbolAddress((void**)&gq,   g_q);
    cudaGetSymbolAddress((void**)&gk,   g_k);
    cudaGetSymbolAddress((void**)&gv,   g_v);
    cudaGetSymbolAddress((void**)&gctx, g_ctx);

    // QKV projections
    gemm128_kernel<<<dim3((NUM_HEADS * HEAD_DIM) / 128, SEQ / 128), 256>>>(
        x, Wq, gq, SEQ, NUM_HEADS * HEAD_DIM, D_IN);
    gemm128_kernel<<<dim3((NUM_KV * HEAD_DIM) / 128, SEQ / 128), 256>>>(
        x, Wk, gk, SEQ, NUM_KV * HEAD_DIM, D_IN);
    gemm128_kernel<<<dim3((NUM_KV * HEAD_DIM) / 128, SEQ / 128), 256>>>(
        x, Wv, gv, SEQ, NUM_KV * HEAD_DIM, D_IN);

    // RMSNorm + RoPE (Q and K)
    norm_rope_kernel<<<SEQ, 128>>>(gq, gk, qsc, ksc, pos);

    // Flash attention
    size_t shmem = (size_t)(FB_M * QSTRIDE + FB_N * QSTRIDE + FB_N * PSTRIDE +
                            FB_M * 16 + 3 * FB_M) * sizeof(float);
    cudaFuncSetAttribute(flash_kernel,
                         cudaFuncAttributeMaxDynamicSharedMemorySize, (int)shmem);
    flash_kernel<<<dim3(SEQ / FB_M, NUM_HEADS), 256, shmem>>>(gq, gk, gv, gctx);

    // Output projection
    gemm128_kernel<<<dim3(D_IN / 128, SEQ / 128), 256>>>(
        gctx, Wo, out, SEQ, D_IN, NUM_HEADS * HEAD_DIM);
}

// round 2
// speedup vs baseline: 3.3082x; 3.3082x over previous
#include <cuda_runtime.h>
#include <math.h>
#include <stdint.h>

#define D_IN       4096
#define NUM_HEADS  32
#define HEAD_DIM   128
#define NUM_KV     8
#define SEQ        2048

// -------- scratch (device globals; no allocation allowed) --------
__device__ float g_q[(size_t)SEQ * NUM_HEADS * HEAD_DIM];
__device__ float g_k[(size_t)SEQ * NUM_KV   * HEAD_DIM];
__device__ float g_v[(size_t)SEQ * NUM_KV   * HEAD_DIM];
__device__ float g_ctx[(size_t)SEQ * NUM_HEADS * HEAD_DIM];

// ---------------- helpers ----------------
__device__ __forceinline__ float tf32r(float x) {
    unsigned r;
    asm("cvt.rna.tf32.f32 %0, %1;" : "=r"(r) : "f"(x));
    return __uint_as_float(r);
}
__device__ __forceinline__ unsigned uu(float x) { return __float_as_uint(x); }

__device__ __forceinline__ void mma8(float* c, unsigned a0, unsigned a1,
                                     unsigned a2, unsigned a3,
                                     unsigned b0, unsigned b1) {
    asm volatile(
        "mma.sync.aligned.m16n8k8.row.col.f32.tf32.tf32.f32 "
        "{%0,%1,%2,%3},{%4,%5,%6,%7},{%8,%9},{%0,%1,%2,%3};\n"
        : "+f"(c[0]), "+f"(c[1]), "+f"(c[2]), "+f"(c[3])
        : "r"(a0), "r"(a1), "r"(a2), "r"(a3), "r"(b0), "r"(b1));
}

// =================================================================
// tf32 GEMM: C[M,N] = A[M,K] @ B[K,N]. BM=BN=128, BK=32,
// 256 threads = 8 warps (4 along M x 2 along N), double-buffered.
// As [m][k] stride 36, Bs [k][n] stride 136 (conflict-free).
// =================================================================
#define GBM 128
#define GBN 128
#define GBK 32
#define AST 36
#define BST 136
#define GEMM_SMEM ((2*GBM*AST + 2*GBK*BST) * 4)

__global__ __launch_bounds__(256) void gemm_tf32_kernel(
    const float* __restrict__ A, const float* __restrict__ B,
    float* __restrict__ C, int M, int N, int K)
{
    extern __shared__ float sm[];
    float* As = sm;                   // [2][128][36]
    float* Bs = sm + 2 * GBM * AST;   // [2][32][136]

    const int tid  = threadIdx.x;
    const int lane = tid & 31;
    const int wid  = tid >> 5;
    const int wm   = wid & 3;         // 0..3  (M)
    const int wn   = wid >> 2;        // 0..1  (N)
    const int lg   = lane >> 2;       // 0..7
    const int lc   = lane & 3;        // 0..3
    const int m0 = blockIdx.y * GBM;
    const int n0 = blockIdx.x * GBN;

    const int arow = tid >> 3;        // 0..31 (+32p)
    const int akq  = tid & 7;         // 0..7
    const int bn4  = tid & 31;        // 0..31
    const int bk   = tid >> 5;        // 0..7 (+8p)

    float c[2][8][4];
#pragma unroll
    for (int i = 0; i < 2; ++i)
#pragma unroll
        for (int j = 0; j < 8; ++j)
#pragma unroll
            for (int e = 0; e < 4; ++e) c[i][j][e] = 0.f;

    const float* Ap = A + (size_t)(m0 + arow) * K + akq * 4;
    const float* Bp = B + (size_t)bk * N + n0 + bn4 * 4;

    float4 ra[4], rb[4];
    const int nst = K / GBK;

    // prologue: load stage 0
#pragma unroll
    for (int p = 0; p < 4; ++p)
        ra[p] = *(const float4*)(Ap + (size_t)(32 * p) * K);
#pragma unroll
    for (int p = 0; p < 4; ++p)
        rb[p] = *(const float4*)(Bp + (size_t)(8 * p) * N);
    {
        float* a = As;
        float* b = Bs;
#pragma unroll
        for (int p = 0; p < 4; ++p) {
            float4 t = make_float4(tf32r(ra[p].x), tf32r(ra[p].y),
                                   tf32r(ra[p].z), tf32r(ra[p].w));
            *(float4*)&a[(arow + 32 * p) * AST + akq * 4] = t;
        }
#pragma unroll
        for (int p = 0; p < 4; ++p) {
            float4 t = make_float4(tf32r(rb[p].x), tf32r(rb[p].y),
                                   tf32r(rb[p].z), tf32r(rb[p].w));
            *(float4*)&b[(bk + 8 * p) * BST + bn4 * 4] = t;
        }
    }
    __syncthreads();

    for (int s = 0; s < nst; ++s) {
        if (s + 1 < nst) {
            int k0 = (s + 1) * GBK;
#pragma unroll
            for (int p = 0; p < 4; ++p)
                ra[p] = *(const float4*)(Ap + (size_t)(32 * p) * K + k0);
#pragma unroll
            for (int p = 0; p < 4; ++p)
                rb[p] = *(const float4*)(Bp + (size_t)(k0 + 8 * p) * N);
        }
        // compute from buf s&1
        const float* a = As + (s & 1) * GBM * AST + (wm * 32) * AST;
        const float* b = Bs + (s & 1) * GBK * BST + wn * 64;
#pragma unroll
        for (int ks = 0; ks < 4; ++ks) {
            unsigned af[2][4];
#pragma unroll
            for (int mt = 0; mt < 2; ++mt) {
                const float* ap = a + (mt * 16 + lg) * AST + ks * 8 + lc;
                af[mt][0] = uu(ap[0]);
                af[mt][1] = uu(ap[8 * AST]);
                af[mt][2] = uu(ap[4]);
                af[mt][3] = uu(ap[8 * AST + 4]);
            }
            unsigned bf[8][2];
#pragma unroll
            for (int nt = 0; nt < 8; ++nt) {
                const float* bp = b + (ks * 8 + lc) * BST + nt * 8 + lg;
                bf[nt][0] = uu(bp[0]);
                bf[nt][1] = uu(bp[4 * BST]);
            }
#pragma unroll
            for (int mt = 0; mt < 2; ++mt)
#pragma unroll
                for (int nt = 0; nt < 8; ++nt)
                    mma8(c[mt][nt], af[mt][0], af[mt][1], af[mt][2], af[mt][3],
                         bf[nt][0], bf[nt][1]);
        }
        if (s + 1 < nst) {
            float* a2 = As + ((s + 1) & 1) * GBM * AST;
            float* b2 = Bs + ((s + 1) & 1) * GBK * BST;
#pragma unroll
            for (int p = 0; p < 4; ++p) {
                float4 t = make_float4(tf32r(ra[p].x), tf32r(ra[p].y),
                                       tf32r(ra[p].z), tf32r(ra[p].w));
                *(float4*)&a2[(arow + 32 * p) * AST + akq * 4] = t;
            }
#pragma unroll
            for (int p = 0; p < 4; ++p) {
                float4 t = make_float4(tf32r(rb[p].x), tf32r(rb[p].y),
                                       tf32r(rb[p].z), tf32r(rb[p].w));
                *(float4*)&b2[(bk + 8 * p) * BST + bn4 * 4] = t;
            }
        }
        __syncthreads();
    }

    // epilogue
#pragma unroll
    for (int mt = 0; mt < 2; ++mt) {
#pragma unroll
        for (int nt = 0; nt < 8; ++nt) {
            int row = m0 + wm * 32 + mt * 16 + lg;
            int col = n0 + wn * 64 + nt * 8 + 2 * lc;
            *(float2*)&C[(size_t)row * N + col] =
                make_float2(c[mt][nt][0], c[mt][nt][1]);
            *(float2*)&C[(size_t)(row + 8) * N + col] =
                make_float2(c[mt][nt][2], c[mt][nt][3]);
        }
    }
}

// =================================================================
// Fused QK-RMSNorm + RoPE (unchanged; 41us)
// =================================================================
__global__ __launch_bounds__(128) void norm_rope_kernel(
    float* __restrict__ q, float* __restrict__ k,
    const float* __restrict__ q_scale, const float* __restrict__ k_scale,
    const int* __restrict__ positions)
{
    const int n = blockIdx.x;
    const int d = threadIdx.x;
    __shared__ float cs[128], sn[128], buf[128], wred[4];

    if (d < 64) {
        double invf = exp2(-(double)d * (13.287712379549449 / 64.0));
        double ang  = (double)positions[n] * invf;
        const double twopi = 6.283185307179586476925287;
        ang -= twopi * floor(ang / twopi);
        float af = (float)ang;
        float c, s;
        sincosf(af, &s, &c);
        cs[d] = c;       sn[d] = s;
        cs[d + 64] = c;  sn[d + 64] = s;
    }
    __syncthreads();

    const int nh = NUM_HEADS + NUM_KV;
    for (int h = 0; h < nh; ++h) {
        float* vec;
        const float* sc;
        if (h < NUM_HEADS) {
            vec = q + ((size_t)n * NUM_HEADS + h) * HEAD_DIM;
            sc = q_scale;
        } else {
            vec = k + ((size_t)n * NUM_KV + (h - NUM_HEADS)) * HEAD_DIM;
            sc = k_scale;
        }
        float val = vec[d];
        float ss = val * val;
#pragma unroll
        for (int o = 16; o > 0; o >>= 1) ss += __shfl_xor_sync(0xffffffffu, ss, o);
        if ((d & 31) == 0) wred[d >> 5] = ss;
        __syncthreads();
        float tot  = wred[0] + wred[1] + wred[2] + wred[3];
        float rinv = rsqrtf(tot * (1.0f / HEAD_DIM) + 1e-6f);
        float nv   = val * rinv * sc[d];
        buf[d] = nv;
        __syncthreads();
        float rot = (d < 64) ? -buf[d + 64] : buf[d - 64];
        vec[d] = fmaf(nv, cs[d], rot * sn[d]);
        __syncthreads();
    }
}

// =================================================================
// Flash attention, tensor-core tf32 (causal, GQA 4:1).
// BM=BN=64, 128 threads (4 warps, warp w owns rows 16w..16w+15).
// Qs stride 132, K stride 132, V stride 136 (shared buffer),
// P stride 68. All fragment LDS patterns bank-conflict-free.
// =================================================================
#define FQST 132
#define FKST 132
#define FVST 136
#define FPST 68
#define FLASH_SMEM ((64*FQST + 64*FVST + 64*FPST) * 4)

__global__ __launch_bounds__(128, 2) void flash_tc_kernel(
    const float* __restrict__ Qg, const float* __restrict__ Kg,
    const float* __restrict__ Vg, float* __restrict__ Og)
{
    extern __shared__ float sm[];
    float* Qs  = sm;                 // 64*132
    float* KVs = Qs + 64 * FQST;     // 64*136 (K then V)
    float* Ps  = KVs + 64 * FVST;    // 64*68

    const int tid  = threadIdx.x;
    const int lane = tid & 31;
    const int w    = tid >> 5;
    const int lg   = lane >> 2;
    const int lc   = lane & 3;
    const int h    = blockIdx.y;
    const int kvh  = h >> 2;
    const int mt   = gridDim.x - 1 - blockIdx.x;   // big tiles first
    const int m0   = mt * 64;
    const float softscale = 0.08838834764831845f;

    // ---- load Q tile (64 x 128) as tf32 ----
#pragma unroll
    for (int it = 0; it < 16; ++it) {
        int id  = tid + it * 128;
        int tok = id >> 5;
        int d4  = id & 31;
        float4 v = *(const float4*)&Qg[((size_t)(m0 + tok) * NUM_HEADS + h) * HEAD_DIM + d4 * 4];
        float4 t = make_float4(tf32r(v.x), tf32r(v.y), tf32r(v.z), tf32r(v.w));
        *(float4*)&Qs[tok * FQST + d4 * 4] = t;
    }

    float o[16][4];
#pragma unroll
    for (int dt = 0; dt < 16; ++dt)
#pragma unroll
        for (int e = 0; e < 4; ++e) o[dt][e] = 0.f;
    float mrun[2] = {-1e30f, -1e30f};
    float lrun[2] = {0.f, 0.f};

    for (int nt = 0; nt <= mt; ++nt) {
        const int n0 = nt * 64;
        __syncthreads();   // prior PV reads of KVs/Ps complete
        // ---- load K tile (stride FKST) ----
#pragma unroll
        for (int it = 0; it < 16; ++it) {
            int id  = tid + it * 128;
            int tok = id >> 5;
            int d4  = id & 31;
            float4 v = *(const float4*)&Kg[((size_t)(n0 + tok) * NUM_KV + kvh) * HEAD_DIM + d4 * 4];
            float4 t = make_float4(tf32r(v.x), tf32r(v.y), tf32r(v.z), tf32r(v.w));
            *(float4*)&KVs[tok * FKST + d4 * 4] = t;
        }
        __syncthreads();

        // ---- S = Q K^T : warp rows 16w.., 8 n-tiles, 16 k-steps ----
        float s[8][4];
#pragma unroll
        for (int n = 0; n < 8; ++n)
#pragma unroll
            for (int e = 0; e < 4; ++e) s[n][e] = 0.f;

#pragma unroll
        for (int ks = 0; ks < 16; ++ks) {
            const float* qp = &Qs[(w * 16 + lg) * FQST + ks * 8 + lc];
            unsigned a0 = uu(qp[0]);
            unsigned a1 = uu(qp[8 * FQST]);
            unsigned a2 = uu(qp[4]);
            unsigned a3 = uu(qp[8 * FQST + 4]);
#pragma unroll
            for (int n = 0; n < 8; ++n) {
                const float* kp = &KVs[(n * 8 + lg) * FKST + ks * 8 + lc];
                mma8(s[n], a0, a1, a2, a3, uu(kp[0]), uu(kp[4]));
            }
        }

        // ---- softmax update ----
        const bool diag = (nt == mt);
        float pmax[2] = {-1e30f, -1e30f};
#pragma unroll
        for (int n = 0; n < 8; ++n) {
#pragma unroll
            for (int e = 0; e < 4; ++e) {
                float v = s[n][e] * softscale;
                if (diag) {
                    int row = w * 16 + lg + (e >> 1) * 8;
                    int col = n * 8 + 2 * lc + (e & 1);
                    if (col > row) v = -1e30f;
                }
                s[n][e] = v;
                pmax[e >> 1] = fmaxf(pmax[e >> 1], v);
            }
        }
#pragma unroll
        for (int half = 0; half < 2; ++half) {
            pmax[half] = fmaxf(pmax[half], __shfl_xor_sync(0xffffffffu, pmax[half], 1));
            pmax[half] = fmaxf(pmax[half], __shfl_xor_sync(0xffffffffu, pmax[half], 2));
        }
        float alpha[2];
#pragma unroll
        for (int half = 0; half < 2; ++half) {
            float nm = fmaxf(mrun[half], pmax[half]);
            alpha[half] = __expf(mrun[half] - nm);
            mrun[half] = nm;
            lrun[half] *= alpha[half];
        }
#pragma unroll
        for (int dt = 0; dt < 16; ++dt) {
            o[dt][0] *= alpha[0]; o[dt][1] *= alpha[0];
            o[dt][2] *= alpha[1]; o[dt][3] *= alpha[1];
        }
        // P = exp(S - m): to regs + smem (tf32), partial row sums
        float lsum[2] = {0.f, 0.f};
#pragma unroll
        for (int n = 0; n < 8; ++n) {
            float p0 = __expf(s[n][0] - mrun[0]);
            float p1 = __expf(s[n][1] - mrun[0]);
            float p2 = __expf(s[n][2] - mrun[1]);
            float p3 = __expf(s[n][3] - mrun[1]);
            lsum[0] += p0 + p1;
            lsum[1] += p2 + p3;
            *(float2*)&Ps[(w * 16 + lg) * FPST + n * 8 + 2 * lc] =
                make_float2(tf32r(p0), tf32r(p1));
            *(float2*)&Ps[(w * 16 + lg + 8) * FPST + n * 8 + 2 * lc] =
                make_float2(tf32r(p2), tf32r(p3));
        }
#pragma unroll
        for (int half = 0; half < 2; ++half) {
            lsum[half] += __shfl_xor_sync(0xffffffffu, lsum[half], 1);
            lsum[half] += __shfl_xor_sync(0xffffffffu, lsum[half], 2);
            lrun[half] += lsum[half];
        }
        __syncthreads();   // all S reads of K done; P visible

        // ---- load V tile (overwrites K buffer, stride FVST) ----
#pragma unroll
        for (int it = 0; it < 16; ++it) {
            int id  = tid + it * 128;
            int tok = id >> 5;
            int d4  = id & 31;
            float4 v = *(const float4*)&Vg[((size_t)(n0 + tok) * NUM_KV + kvh) * HEAD_DIM + d4 * 4];
            float4 t = make_float4(tf32r(v.x), tf32r(v.y), tf32r(v.z), tf32r(v.w));
            *(float4*)&KVs[tok * FVST + d4 * 4] = t;
        }
        __syncthreads();

        // ---- O += P V : 16 d-tiles, 8 k-steps ----
#pragma unroll
        for (int ks = 0; ks < 8; ++ks) {
            const float* pp = &Ps[(w * 16 + lg) * FPST + ks * 8 + lc];
            unsigned a0 = uu(pp[0]);
            unsigned a1 = uu(pp[8 * FPST]);
            unsigned a2 = uu(pp[4]);
            unsigned a3 = uu(pp[8 * FPST + 4]);
#pragma unroll
            for (int dt = 0; dt < 16; ++dt) {
                const float* vp = &KVs[(ks * 8 + lc) * FVST + dt * 8 + lg];
                mma8(o[dt], a0, a1, a2, a3, uu(vp[0]), uu(vp[4 * FVST]));
            }
        }
    }

    // ---- finalize ----
    float inv0 = 1.f / lrun[0];
    float inv1 = 1.f / lrun[1];
#pragma unroll
    for (int dt = 0; dt < 16; ++dt) {
        int row = m0 + w * 16 + lg;
        int col = dt * 8 + 2 * lc;
        *(float2*)&Og[((size_t)row * NUM_HEADS + h) * HEAD_DIM + col] =
            make_float2(o[dt][0] * inv0, o[dt][1] * inv0);
        *(float2*)&Og[((size_t)(row + 8) * NUM_HEADS + h) * HEAD_DIM + col] =
            make_float2(o[dt][2] * inv1, o[dt][3] * inv1);
    }
}

// =================================================================
// kernel_launch
// =================================================================
extern "C" void kernel_launch(void* const* d_in, const int* in_sizes, int n_in,
                              void* d_out, int out_size)
{
    const float* x   = (const float*)d_in[0];
    const int*   pos = (const int*)  d_in[1];
    const float* Wq  = (const float*)d_in[2];
    const float* Wk  = (const float*)d_in[3];
    const float* Wv  = (const float*)d_in[4];
    const float* Wo  = (const float*)d_in[5];
    const float* qsc = (const float*)d_in[6];
    const float* ksc = (const float*)d_in[7];
    float* out = (float*)d_out;

    float *gq, *gk, *gv, *gctx;
    cudaGetSymbolAddress((void**)&gq,   g_q);
    cudaGetSymbolAddress((void**)&gk,   g_k);
    cudaGetSymbolAddress((void**)&gv,   g_v);
    cudaGetSymbolAddress((void**)&gctx, g_ctx);

    cudaFuncSetAttribute(gemm_tf32_kernel,
                         cudaFuncAttributeMaxDynamicSharedMemorySize, GEMM_SMEM);
    cudaFuncSetAttribute(flash_tc_kernel,
                         cudaFuncAttributeMaxDynamicSharedMemorySize, FLASH_SMEM);

    // QKV projections (tf32 tensor cores)
    gemm_tf32_kernel<<<dim3((NUM_HEADS * HEAD_DIM) / GBN, SEQ / GBM), 256, GEMM_SMEM>>>(
        x, Wq, gq, SEQ, NUM_HEADS * HEAD_DIM, D_IN);
    gemm_tf32_kernel<<<dim3((NUM_KV * HEAD_DIM) / GBN, SEQ / GBM), 256, GEMM_SMEM>>>(
        x, Wk, gk, SEQ, NUM_KV * HEAD_DIM, D_IN);
    gemm_tf32_kernel<<<dim3((NUM_KV * HEAD_DIM) / GBN, SEQ / GBM), 256, GEMM_SMEM>>>(
        x, Wv, gv, SEQ, NUM_KV * HEAD_DIM, D_IN);

    // RMSNorm + RoPE
    norm_rope_kernel<<<SEQ, 128>>>(gq, gk, qsc, ksc, pos);

    // Flash attention (tf32 tensor cores)
    flash_tc_kernel<<<dim3(SEQ / 64, NUM_HEADS), 128, FLASH_SMEM>>>(gq, gk, gv, gctx);

    // Output projection
    gemm_tf32_kernel<<<dim3(D_IN / GBN, SEQ / GBM), 256, GEMM_SMEM>>>(
        gctx, Wo, out, SEQ, D_IN, NUM_HEADS * HEAD_DIM);
}

// round 4
// speedup vs baseline: 6.8335x; 2.0657x over previous
#include <cuda_runtime.h>
#include <cuda_fp16.h>
#include <math.h>
#include <stdint.h>

#define D_IN       4096
#define NUM_HEADS  32
#define HEAD_DIM   128
#define NUM_KV     8
#define SEQ        2048

// -------- scratch (device globals; no allocation allowed) --------
__device__ float  g_q  [(size_t)SEQ * NUM_HEADS * HEAD_DIM];     // fp32 Q (pre-norm)
__device__ float  g_k  [(size_t)SEQ * NUM_KV   * HEAD_DIM];      // fp32 K (pre-norm)
__device__ __half g_qh [(size_t)SEQ * NUM_HEADS * HEAD_DIM];     // normed+roped, fp16
__device__ __half g_kh [(size_t)SEQ * NUM_KV   * HEAD_DIM];
__device__ __half g_vh [(size_t)SEQ * NUM_KV   * HEAD_DIM];
__device__ __half g_ctxh[(size_t)SEQ * NUM_HEADS * HEAD_DIM];
__device__ __half g_xh [(size_t)SEQ * D_IN];
__device__ __half g_wqT[(size_t)(NUM_HEADS*HEAD_DIM) * D_IN];    // [N][K] fp16
__device__ __half g_wkT[(size_t)(NUM_KV*HEAD_DIM)   * D_IN];
__device__ __half g_wvT[(size_t)(NUM_KV*HEAD_DIM)   * D_IN];
__device__ __half g_woT[(size_t)D_IN * (NUM_HEADS*HEAD_DIM)];

// ---------------- helpers ----------------
__device__ __forceinline__ uint32_t smem_u32(const void* p) {
    uint32_t a;
    asm("{ .reg .u64 t; cvta.to.shared.u64 t, %1; cvt.u32.u64 %0, t; }"
        : "=r"(a) : "l"(p));
    return a;
}
__device__ __forceinline__ void cp16(uint32_t d, const void* s) {
    asm volatile("cp.async.cg.shared.global [%0], [%1], 16;"
                 :: "r"(d), "l"(s) : "memory");
}
#define CP_COMMIT() asm volatile("cp.async.commit_group;" ::: "memory")
#define CP_WAIT1()  asm volatile("cp.async.wait_group 1;" ::: "memory")

__device__ __forceinline__ void mma16(float* c, const uint32_t* a,
                                      uint32_t b0, uint32_t b1) {
    asm volatile(
        "mma.sync.aligned.m16n8k16.row.col.f32.f16.f16.f32 "
        "{%0,%1,%2,%3},{%4,%5,%6,%7},{%8,%9},{%0,%1,%2,%3};\n"
        : "+f"(c[0]), "+f"(c[1]), "+f"(c[2]), "+f"(c[3])
        : "r"(a[0]), "r"(a[1]), "r"(a[2]), "r"(a[3]), "r"(b0), "r"(b1));
}
__device__ __forceinline__ uint32_t ldu32(const __half* p) {
    return *(const uint32_t*)p;
}
__device__ __forceinline__ uint32_t h2bits(__half2 h) {
    return *(uint32_t*)&h;
}

// =================================================================
// fp16 GEMM: C[M,N] = A[M,K] @ Bt^T, A [M][K] half, Bt [N][K] half.
// BM=BN=128, BK=64, 256 threads (8 warps: 4M x 2N), 3-stage cp.async.
// smem stride 72 halves (144B) -> conflict-free frags & 16B cp.async.
// =================================================================
#define GST 72
#define GSTAGE_BYTES 36864            // (128*72 A + 128*72 B) * 2B
#define GEMM_SMEM (3 * GSTAGE_BYTES)  // 110592

template<bool HALF_OUT>
__global__ __launch_bounds__(256) void gemm_f16(
    const __half* __restrict__ A, const __half* __restrict__ B,
    void* __restrict__ Cv, int M, int N, int K)
{
    extern __shared__ __half sh[];
    const uint32_t sb = smem_u32(sh);
    const int tid = threadIdx.x;
    const int lane = tid & 31, wid = tid >> 5;
    const int wm = wid & 3, wn = wid >> 2;
    const int lg = lane >> 2, lc = lane & 3;
    const int m0 = blockIdx.y * 128, n0 = blockIdx.x * 128;
    const int nsteps = K / 64;
    const int lrow = tid >> 3;   // 0..31
    const int lchk = tid & 7;    // 0..7

    float acc[2][8][4];
#pragma unroll
    for (int i = 0; i < 2; ++i)
#pragma unroll
        for (int j = 0; j < 8; ++j)
#pragma unroll
            for (int e = 0; e < 4; ++e) acc[i][j][e] = 0.f;

    const __half* Ag = A + (size_t)m0 * K;
    const __half* Bg = B + (size_t)n0 * K;

#define LOAD_STAGE(s, k0) do {                                            \
    uint32_t as_ = sb + (uint32_t)(s) * GSTAGE_BYTES;                     \
    uint32_t bs_ = as_ + 18432;                                           \
    _Pragma("unroll")                                                     \
    for (int j_ = 0; j_ < 4; ++j_) {                                      \
        int row_ = lrow + 32 * j_;                                        \
        cp16(as_ + row_ * 144 + lchk * 16,                                \
             Ag + (size_t)row_ * K + (k0) + lchk * 8);                    \
        cp16(bs_ + row_ * 144 + lchk * 16,                                \
             Bg + (size_t)row_ * K + (k0) + lchk * 8);                    \
    }                                                                     \
} while (0)

    LOAD_STAGE(0, 0);  CP_COMMIT();
    LOAD_STAGE(1, 64); CP_COMMIT();

    for (int s = 0; s < nsteps; ++s) {
        CP_WAIT1();
        __syncthreads();
        if (s + 2 < nsteps) {
            int sn = s + 2; int bufn = sn - (sn / 3) * 3;
            LOAD_STAGE(bufn, sn * 64);
        }
        CP_COMMIT();

        const int buf = s - (s / 3) * 3;
        const __half* Ah = sh + (size_t)buf * 18432;
        const __half* Bh = Ah + 9216;
#pragma unroll
        for (int ks = 0; ks < 4; ++ks) {
            uint32_t af[2][4];
#pragma unroll
            for (int mt = 0; mt < 2; ++mt) {
                const __half* p = Ah + (wm * 32 + mt * 16 + lg) * GST + ks * 16 + 2 * lc;
                af[mt][0] = ldu32(p);
                af[mt][1] = ldu32(p + 8 * GST);
                af[mt][2] = ldu32(p + 8);
                af[mt][3] = ldu32(p + 8 * GST + 8);
            }
#pragma unroll
            for (int nt = 0; nt < 8; ++nt) {
                const __half* p = Bh + (wn * 64 + nt * 8 + lg) * GST + ks * 16 + 2 * lc;
                uint32_t b0 = ldu32(p), b1 = ldu32(p + 8);
                mma16(acc[0][nt], af[0], b0, b1);
                mma16(acc[1][nt], af[1], b0, b1);
            }
        }
    }
#undef LOAD_STAGE

    // epilogue
#pragma unroll
    for (int mt = 0; mt < 2; ++mt) {
#pragma unroll
        for (int nt = 0; nt < 8; ++nt) {
            int row = m0 + wm * 32 + mt * 16 + lg;
            int col = n0 + wn * 64 + nt * 8 + 2 * lc;
            if (HALF_OUT) {
                __half* C = (__half*)Cv;
                *(__half2*)&C[(size_t)row * N + col] =
                    __floats2half2_rn(acc[mt][nt][0], acc[mt][nt][1]);
                *(__half2*)&C[(size_t)(row + 8) * N + col] =
                    __floats2half2_rn(acc[mt][nt][2], acc[mt][nt][3]);
            } else {
                float* C = (float*)Cv;
                *(float2*)&C[(size_t)row * N + col] =
                    make_float2(acc[mt][nt][0], acc[mt][nt][1]);
                *(float2*)&C[(size_t)(row + 8) * N + col] =
                    make_float2(acc[mt][nt][2], acc[mt][nt][3]);
            }
        }
    }
}

// =================================================================
// pre-pass: fp32 -> fp16 copy; fp32 [K][N] -> fp16 [N][K] transpose
// =================================================================
__global__ __launch_bounds__(256) void to_half_kernel(
    const float* __restrict__ in, __half* __restrict__ out, int n4)
{
    int i = blockIdx.x * blockDim.x + threadIdx.x;
    int stride = gridDim.x * blockDim.x;
    for (; i < n4; i += stride) {
        float4 v = ((const float4*)in)[i];
        __half2 h0 = __floats2half2_rn(v.x, v.y);
        __half2 h1 = __floats2half2_rn(v.z, v.w);
        ((uint2*)out)[i] = make_uint2(h2bits(h0), h2bits(h1));
    }
}

__global__ __launch_bounds__(256) void transpose_half_kernel(
    const float* __restrict__ W, __half* __restrict__ WT, int K, int N)
{
    __shared__ float s[32][33];
    const int tid = threadIdx.x;
    const int k0 = blockIdx.y * 32;
    const int n0 = blockIdx.x * 32;
    {
        int rk = tid >> 3;
        int cn = tid & 7;
        float4 v = *(const float4*)&W[(size_t)(k0 + rk) * N + n0 + cn * 4];
        s[rk][cn*4+0] = v.x; s[rk][cn*4+1] = v.y;
        s[rk][cn*4+2] = v.z; s[rk][cn*4+3] = v.w;
    }
    __syncthreads();
    {
        int rn = tid >> 3;
        int ck = tid & 7;
        __half2 h0 = __floats2half2_rn(s[ck*4+0][rn], s[ck*4+1][rn]);
        __half2 h1 = __floats2half2_rn(s[ck*4+2][rn], s[ck*4+3][rn]);
        *(uint2*)&WT[(size_t)(n0 + rn) * K + k0 + ck * 4] =
            make_uint2(h2bits(h0), h2bits(h1));
    }
}

// =================================================================
// Fused QK-RMSNorm + RoPE; fp32 in, fp16 out.
// =================================================================
__global__ __launch_bounds__(128) void norm_rope_kernel(
    const float* __restrict__ qin, const float* __restrict__ kin,
    __half* __restrict__ qout, __half* __restrict__ kout,
    const float* __restrict__ q_scale, const float* __restrict__ k_scale,
    const int* __restrict__ positions)
{
    const int n = blockIdx.x;
    const int d = threadIdx.x;
    __shared__ float cs[128], sn[128], buf[128], wred[4];

    if (d < 64) {
        double invf = exp2(-(double)d * (13.287712379549449 / 64.0));
        double ang  = (double)positions[n] * invf;
        const double twopi = 6.283185307179586476925287;
        ang -= twopi * floor(ang / twopi);
        float af = (float)ang;
        float c, s;
        sincosf(af, &s, &c);
        cs[d] = c;       sn[d] = s;
        cs[d + 64] = c;  sn[d + 64] = s;
    }
    __syncthreads();

    const int nh = NUM_HEADS + NUM_KV;
    for (int h = 0; h < nh; ++h) {
        const float* vec;
        __half* vecout;
        const float* sc;
        if (h < NUM_HEADS) {
            vec    = qin  + ((size_t)n * NUM_HEADS + h) * HEAD_DIM;
            vecout = qout + ((size_t)n * NUM_HEADS + h) * HEAD_DIM;
            sc = q_scale;
        } else {
            vec    = kin  + ((size_t)n * NUM_KV + (h - NUM_HEADS)) * HEAD_DIM;
            vecout = kout + ((size_t)n * NUM_KV + (h - NUM_HEADS)) * HEAD_DIM;
            sc = k_scale;
        }
        float val = vec[d];
        float ss = val * val;
#pragma unroll
        for (int o = 16; o > 0; o >>= 1) ss += __shfl_xor_sync(0xffffffffu, ss, o);
        if ((d & 31) == 0) wred[d >> 5] = ss;
        __syncthreads();
        float tot  = wred[0] + wred[1] + wred[2] + wred[3];
        float rinv = rsqrtf(tot * (1.0f / HEAD_DIM) + 1e-6f);
        float nv   = val * rinv * sc[d];
        buf[d] = nv;
        __syncthreads();
        float rot = (d < 64) ? -buf[d + 64] : buf[d - 64];
        vecout[d] = __float2half_rn(fmaf(nv, cs[d], rot * sn[d]));
        __syncthreads();
    }
}

// =================================================================
// Flash attention, fp16 mma (causal, GQA 4:1). BM=BN=64, 128 thr.
// Qs/K/V stride 136 halves; P stride 72; PV B-frag via
// ldmatrix.m8n8.x2.trans from V stored [tok][d].
// =================================================================
#define FST 136
#define PST 72
#define FLASH_SMEM ((64*FST + 64*FST + 64*PST) * 2)   // 44032 B

__global__ __launch_bounds__(128, 2) void flash_f16_kernel(
    const __half* __restrict__ Qh, const __half* __restrict__ Kh,
    const __half* __restrict__ Vh, __half* __restrict__ Oh)
{
    extern __shared__ __half fsm[];
    __half* Qs  = fsm;               // 64 x 136
    __half* KVs = Qs + 64 * FST;     // 64 x 136 (K, then V)
    __half* Ps  = KVs + 64 * FST;    // 64 x 72
    const uint32_t kvs_addr = smem_u32(KVs);

    const int tid  = threadIdx.x;
    const int lane = tid & 31;
    const int w    = tid >> 5;
    const int lg   = lane >> 2;
    const int lc   = lane & 3;
    const int h    = blockIdx.y;
    const int kvh  = h >> 2;
    const int mt   = gridDim.x - 1 - blockIdx.x;
    const int m0   = mt * 64;
    const float softscale = 0.08838834764831845f;

    // ---- load Q tile (64 x 128 halves) ----
#pragma unroll
    for (int it = 0; it < 8; ++it) {
        int id  = tid + it * 128;
        int tok = id >> 4;
        int u   = id & 15;
        *(uint4*)&Qs[tok * FST + u * 8] =
            *(const uint4*)&Qh[((size_t)(m0 + tok) * NUM_HEADS + h) * HEAD_DIM + u * 8];
    }

    float o[16][4];
#pragma unroll
    for (int dt = 0; dt < 16; ++dt)
#pragma unroll
        for (int e = 0; e < 4; ++e) o[dt][e] = 0.f;
    float mrun[2] = {-1e30f, -1e30f};
    float lrun[2] = {0.f, 0.f};

    for (int nt = 0; nt <= mt; ++nt) {
        const int n0 = nt * 64;
        __syncthreads();   // prior PV reads of KVs/Ps done
        // ---- load K tile ----
#pragma unroll
        for (int it = 0; it < 8; ++it) {
            int id  = tid + it * 128;
            int tok = id >> 4;
            int u   = id & 15;
            *(uint4*)&KVs[tok * FST + u * 8] =
                *(const uint4*)&Kh[((size_t)(n0 + tok) * NUM_KV + kvh) * HEAD_DIM + u * 8];
        }
        __syncthreads();

        // ---- S = Q K^T ----
        float s[8][4];
#pragma unroll
        for (int n = 0; n < 8; ++n)
#pragma unroll
            for (int e = 0; e < 4; ++e) s[n][e] = 0.f;

#pragma unroll
        for (int ks = 0; ks < 8; ++ks) {
            const __half* qp = Qs + (w * 16 + lg) * FST + ks * 16 + 2 * lc;
            uint32_t af[4];
            af[0] = ldu32(qp);
            af[1] = ldu32(qp + 8 * FST);
            af[2] = ldu32(qp + 8);
            af[3] = ldu32(qp + 8 * FST + 8);
#pragma unroll
            for (int n = 0; n < 8; ++n) {
                const __half* kp = KVs + (n * 8 + lg) * FST + ks * 16 + 2 * lc;
                mma16(s[n], af, ldu32(kp), ldu32(kp + 8));
            }
        }

        // ---- softmax update ----
        const bool diag = (nt == mt);
        float pmax[2] = {-1e30f, -1e30f};
#pragma unroll
        for (int n = 0; n < 8; ++n) {
#pragma unroll
            for (int e = 0; e < 4; ++e) {
                float v = s[n][e] * softscale;
                if (diag) {
                    int row = w * 16 + lg + (e >> 1) * 8;
                    int col = n * 8 + 2 * lc + (e & 1);
                    if (col > row) v = -1e30f;
                }
                s[n][e] = v;
                pmax[e >> 1] = fmaxf(pmax[e >> 1], v);
            }
        }
#pragma unroll
        for (int half = 0; half < 2; ++half) {
            pmax[half] = fmaxf(pmax[half], __shfl_xor_sync(0xffffffffu, pmax[half], 1));
            pmax[half] = fmaxf(pmax[half], __shfl_xor_sync(0xffffffffu, pmax[half], 2));
        }
        float alpha[2];
#pragma unroll
        for (int half = 0; half < 2; ++half) {
            float nm = fmaxf(mrun[half], pmax[half]);
            alpha[half] = __expf(mrun[half] - nm);
            mrun[half] = nm;
            lrun[half] *= alpha[half];
        }
#pragma unroll
        for (int dt = 0; dt < 16; ++dt) {
            o[dt][0] *= alpha[0]; o[dt][1] *= alpha[0];
            o[dt][2] *= alpha[1]; o[dt][3] *= alpha[1];
        }
        // P = exp(S - m) -> fp16 smem, partial row sums
        float lsum[2] = {0.f, 0.f};
#pragma unroll
        for (int n = 0; n < 8; ++n) {
            float p0 = __expf(s[n][0] - mrun[0]);
            float p1 = __expf(s[n][1] - mrun[0]);
            float p2 = __expf(s[n][2] - mrun[1]);
            float p3 = __expf(s[n][3] - mrun[1]);
            lsum[0] += p0 + p1;
            lsum[1] += p2 + p3;
            *(__half2*)&Ps[(w * 16 + lg) * PST + n * 8 + 2 * lc] =
                __floats2half2_rn(p0, p1);
            *(__half2*)&Ps[(w * 16 + lg + 8) * PST + n * 8 + 2 * lc] =
                __floats2half2_rn(p2, p3);
        }
#pragma unroll
        for (int half = 0; half < 2; ++half) {
            lsum[half] += __shfl_xor_sync(0xffffffffu, lsum[half], 1);
            lsum[half] += __shfl_xor_sync(0xffffffffu, lsum[half], 2);
            lrun[half] += lsum[half];
        }
        __syncthreads();   // S reads of K done; P visible

        // ---- load V tile (overwrites K buffer; [tok][d]) ----
#pragma unroll
        for (int it = 0; it < 8; ++it) {
            int id  = tid + it * 128;
            int tok = id >> 4;
            int u   = id & 15;
            *(uint4*)&KVs[tok * FST + u * 8] =
                *(const uint4*)&Vh[((size_t)(n0 + tok) * NUM_KV + kvh) * HEAD_DIM + u * 8];
        }
        __syncthreads();

        // ---- O += P V (B-frag via ldmatrix.x2.trans) ----
#pragma unroll
        for (int ks = 0; ks < 4; ++ks) {
            const __half* pp = Ps + (w * 16 + lg) * PST + ks * 16 + 2 * lc;
            uint32_t af[4];
            af[0] = ldu32(pp);
            af[1] = ldu32(pp + 8 * PST);
            af[2] = ldu32(pp + 8);
            af[3] = ldu32(pp + 8 * PST + 8);
            uint32_t vrow = kvs_addr + ((uint32_t)(ks * 16 + (lane & 15))) * (FST * 2);
#pragma unroll
            for (int dt = 0; dt < 16; ++dt) {
                uint32_t r0, r1;
                asm volatile(
                    "ldmatrix.sync.aligned.m8n8.x2.trans.shared.b16 {%0,%1}, [%2];"
                    : "=r"(r0), "=r"(r1) : "r"(vrow + dt * 16));
                mma16(o[dt], af, r0, r1);
            }
        }
    }

    // ---- finalize ----
    float inv0 = 1.f / lrun[0];
    float inv1 = 1.f / lrun[1];
#pragma unroll
    for (int dt = 0; dt < 16; ++dt) {
        int row = m0 + w * 16 + lg;
        int col = dt * 8 + 2 * lc;
        *(__half2*)&Oh[((size_t)row * NUM_HEADS + h) * HEAD_DIM + col] =
            __floats2half2_rn(o[dt][0] * inv0, o[dt][1] * inv0);
        *(__half2*)&Oh[((size_t)(row + 8) * NUM_HEADS + h) * HEAD_DIM + col] =
            __floats2half2_rn(o[dt][2] * inv1, o[dt][3] * inv1);
    }
}

// =================================================================
// kernel_launch
// =================================================================
extern "C" void kernel_launch(void* const* d_in, const int* in_sizes, int n_in,
                              void* d_out, int out_size)
{
    const float* x   = (const float*)d_in[0];
    const int*   pos = (const int*)  d_in[1];
    const float* Wq  = (const float*)d_in[2];
    const float* Wk  = (const float*)d_in[3];
    const float* Wv  = (const float*)d_in[4];
    const float* Wo  = (const float*)d_in[5];
    const float* qsc = (const float*)d_in[6];
    const float* ksc = (const float*)d_in[7];
    float* out = (float*)d_out;

    float *gq, *gk;
    __half *gqh, *gkh, *gvh, *gctxh, *gxh, *gwqT, *gwkT, *gwvT, *gwoT;
    cudaGetSymbolAddress((void**)&gq,    g_q);
    cudaGetSymbolAddress((void**)&gk,    g_k);
    cudaGetSymbolAddress((void**)&gqh,   g_qh);
    cudaGetSymbolAddress((void**)&gkh,   g_kh);
    cudaGetSymbolAddress((void**)&gvh,   g_vh);
    cudaGetSymbolAddress((void**)&gctxh, g_ctxh);
    cudaGetSymbolAddress((void**)&gxh,   g_xh);
    cudaGetSymbolAddress((void**)&gwqT,  g_wqT);
    cudaGetSymbolAddress((void**)&gwkT,  g_wkT);
    cudaGetSymbolAddress((void**)&gwvT,  g_wvT);
    cudaGetSymbolAddress((void**)&gwoT,  g_woT);

    const int NQ = NUM_HEADS * HEAD_DIM;   // 4096
    const int NK = NUM_KV * HEAD_DIM;      // 1024

    cudaFuncSetAttribute(gemm_f16<false>,
                         cudaFuncAttributeMaxDynamicSharedMemorySize, GEMM_SMEM);
    cudaFuncSetAttribute(gemm_f16<true>,
                         cudaFuncAttributeMaxDynamicSharedMemorySize, GEMM_SMEM);
    cudaFuncSetAttribute(flash_f16_kernel,
                         cudaFuncAttributeMaxDynamicSharedMemorySize, FLASH_SMEM);

    // ---- pre-pass: fp16 conversions ----
    to_half_kernel<<<1024, 256>>>(x, gxh, (SEQ * D_IN) / 4);
    transpose_half_kernel<<<dim3(NQ / 32, D_IN / 32), 256>>>(Wq, gwqT, D_IN, NQ);
    transpose_half_kernel<<<dim3(NK / 32, D_IN / 32), 256>>>(Wk, gwkT, D_IN, NK);
    transpose_half_kernel<<<dim3(NK / 32, D_IN / 32), 256>>>(Wv, gwvT, D_IN, NK);
    transpose_half_kernel<<<dim3(D_IN / 32, NQ / 32), 256>>>(Wo, gwoT, NQ, D_IN);

    // ---- QKV projections (fp16 tensor cores) ----
    gemm_f16<false><<<dim3(NQ / 128, SEQ / 128), 256, GEMM_SMEM>>>(
        gxh, gwqT, gq, SEQ, NQ, D_IN);
    gemm_f16<false><<<dim3(NK / 128, SEQ / 128), 256, GEMM_SMEM>>>(
        gxh, gwkT, gk, SEQ, NK, D_IN);
    gemm_f16<true><<<dim3(NK / 128, SEQ / 128), 256, GEMM_SMEM>>>(
        gxh, gwvT, gvh, SEQ, NK, D_IN);

    // ---- RMSNorm + RoPE (fp32 -> fp16) ----
    norm_rope_kernel<<<SEQ, 128>>>(gq, gk, gqh, gkh, qsc, ksc, pos);

    // ---- Flash attention (fp16) ----
    flash_f16_kernel<<<dim3(SEQ / 64, NUM_HEADS), 128, FLASH_SMEM>>>(
        gqh, gkh, gvh, gctxh);

    // ---- Output projection ----
    gemm_f16<false><<<dim3(D_IN / 128, SEQ / 128), 256, GEMM_SMEM>>>(
        gctxh, gwoT, out, SEQ, D_IN, NQ);
}

// round 5
// speedup vs baseline: 7.2858x; 1.0662x over previous
#include <cuda_runtime.h>
#include <cuda_fp16.h>
#include <math.h>
#include <stdint.h>

#define D_IN       4096
#define NUM_HEADS  32
#define HEAD_DIM   128
#define NUM_KV     8
#define SEQ        2048

// -------- scratch (device globals; no allocation allowed) --------
__device__ float  g_q  [(size_t)SEQ * NUM_HEADS * HEAD_DIM];
__device__ float  g_k  [(size_t)SEQ * NUM_KV   * HEAD_DIM];
__device__ __half g_qh [(size_t)SEQ * NUM_HEADS * HEAD_DIM];
__device__ __half g_kh [(size_t)SEQ * NUM_KV   * HEAD_DIM];
__device__ __half g_vh [(size_t)SEQ * NUM_KV   * HEAD_DIM];
__device__ __half g_ctxh[(size_t)SEQ * NUM_HEADS * HEAD_DIM];
__device__ __half g_xh [(size_t)SEQ * D_IN];
__device__ __half g_wqT[(size_t)(NUM_HEADS*HEAD_DIM) * D_IN];
__device__ __half g_wkT[(size_t)(NUM_KV*HEAD_DIM)   * D_IN];
__device__ __half g_wvT[(size_t)(NUM_KV*HEAD_DIM)   * D_IN];
__device__ __half g_woT[(size_t)D_IN * (NUM_HEADS*HEAD_DIM)];

// ---------------- helpers ----------------
__device__ __forceinline__ uint32_t smem_u32(const void* p) {
    uint32_t a;
    asm("{ .reg .u64 t; cvta.to.shared.u64 t, %1; cvt.u32.u64 %0, t; }"
        : "=r"(a) : "l"(p));
    return a;
}
__device__ __forceinline__ void cp16(uint32_t d, const void* s) {
    asm volatile("cp.async.cg.shared.global [%0], [%1], 16;"
                 :: "r"(d), "l"(s) : "memory");
}
#define CP_COMMIT() asm volatile("cp.async.commit_group;" ::: "memory")
#define CP_WAIT1()  asm volatile("cp.async.wait_group 1;" ::: "memory")

__device__ __forceinline__ void mma16(float* c, const uint32_t* a,
                                      uint32_t b0, uint32_t b1) {
    asm volatile(
        "mma.sync.aligned.m16n8k16.row.col.f32.f16.f16.f32 "
        "{%0,%1,%2,%3},{%4,%5,%6,%7},{%8,%9},{%0,%1,%2,%3};\n"
        : "+f"(c[0]), "+f"(c[1]), "+f"(c[2]), "+f"(c[3])
        : "r"(a[0]), "r"(a[1]), "r"(a[2]), "r"(a[3]), "r"(b0), "r"(b1));
}
__device__ __forceinline__ void ldsm4(uint32_t addr, uint32_t& r0, uint32_t& r1,
                                      uint32_t& r2, uint32_t& r3) {
    asm volatile("ldmatrix.sync.aligned.m8n8.x4.shared.b16 {%0,%1,%2,%3}, [%4];"
                 : "=r"(r0), "=r"(r1), "=r"(r2), "=r"(r3) : "r"(addr));
}
__device__ __forceinline__ uint32_t ldu32(const __half* p) {
    return *(const uint32_t*)p;
}
__device__ __forceinline__ uint32_t h2bits(__half2 h) {
    return *(uint32_t*)&h;
}

// =================================================================
// fp16 GEMM: C[M,N] = A[M,K] @ Bt^T. BM=BN=128, BK=64, 256 thr,
// 3-stage cp.async, fragments via ldmatrix.x4. smem stride 72 half.
// =================================================================
#define GST 72
#define GSTAGE_BYTES 36864
#define GEMM_SMEM (3 * GSTAGE_BYTES)

template<bool HALF_OUT>
__global__ __launch_bounds__(256) void gemm_f16(
    const __half* __restrict__ A, const __half* __restrict__ B,
    void* __restrict__ Cv, int M, int N, int K)
{
    extern __shared__ __half sh[];
    const uint32_t sb = smem_u32(sh);
    const int tid = threadIdx.x;
    const int lane = tid & 31, wid = tid >> 5;
    const int wm = wid & 3, wn = wid >> 2;
    const int lg = lane >> 2, lc = lane & 3;
    const int m0 = blockIdx.y * 128, n0 = blockIdx.x * 128;
    const int nsteps = K / 64;
    const int lrow = tid >> 3;
    const int lchk = tid & 7;

    // per-lane ldmatrix byte offsets within a stage
    const uint32_t a_off = (uint32_t)((wm * 32 + (lane & 15)) * 144 + (lane >> 4) * 16);
    const uint32_t b_off = (uint32_t)(18432 +
        (wn * 64 + (lane & 7) + ((lane >> 4) * 8)) * 144 + ((lane >> 3) & 1) * 16);

    float acc[2][8][4];
#pragma unroll
    for (int i = 0; i < 2; ++i)
#pragma unroll
        for (int j = 0; j < 8; ++j)
#pragma unroll
            for (int e = 0; e < 4; ++e) acc[i][j][e] = 0.f;

    const __half* Ag = A + (size_t)m0 * K;
    const __half* Bg = B + (size_t)n0 * K;

#define LOAD_STAGE(s, k0) do {                                            \
    uint32_t as_ = sb + (uint32_t)(s) * GSTAGE_BYTES;                     \
    uint32_t bs_ = as_ + 18432;                                           \
    _Pragma("unroll")                                                     \
    for (int j_ = 0; j_ < 4; ++j_) {                                      \
        int row_ = lrow + 32 * j_;                                        \
        cp16(as_ + row_ * 144 + lchk * 16,                                \
             Ag + (size_t)row_ * K + (k0) + lchk * 8);                    \
        cp16(bs_ + row_ * 144 + lchk * 16,                                \
             Bg + (size_t)row_ * K + (k0) + lchk * 8);                    \
    }                                                                     \
} while (0)

    LOAD_STAGE(0, 0);  CP_COMMIT();
    LOAD_STAGE(1, 64); CP_COMMIT();

    for (int s = 0; s < nsteps; ++s) {
        CP_WAIT1();
        __syncthreads();
        if (s + 2 < nsteps) {
            int sn = s + 2; int bufn = sn - (sn / 3) * 3;
            LOAD_STAGE(bufn, sn * 64);
        }
        CP_COMMIT();

        const int buf = s - (s / 3) * 3;
        const uint32_t st = sb + (uint32_t)buf * GSTAGE_BYTES;
#pragma unroll
        for (int ks = 0; ks < 4; ++ks) {
            uint32_t af[2][4];
            ldsm4(st + a_off + ks * 32,            af[0][0], af[0][1], af[0][2], af[0][3]);
            ldsm4(st + a_off + ks * 32 + 16 * 144, af[1][0], af[1][1], af[1][2], af[1][3]);
            uint32_t bf[8][2];
#pragma unroll
            for (int ntp = 0; ntp < 4; ++ntp) {
                uint32_t r0, r1, r2, r3;
                ldsm4(st + b_off + ks * 32 + ntp * 16 * 144, r0, r1, r2, r3);
                bf[2*ntp][0] = r0; bf[2*ntp][1] = r1;
                bf[2*ntp+1][0] = r2; bf[2*ntp+1][1] = r3;
            }
#pragma unroll
            for (int nt = 0; nt < 8; ++nt) {
                mma16(acc[0][nt], af[0], bf[nt][0], bf[nt][1]);
                mma16(acc[1][nt], af[1], bf[nt][0], bf[nt][1]);
            }
        }
    }
#undef LOAD_STAGE

#pragma unroll
    for (int mt = 0; mt < 2; ++mt) {
#pragma unroll
        for (int nt = 0; nt < 8; ++nt) {
            int row = m0 + wm * 32 + mt * 16 + lg;
            int col = n0 + wn * 64 + nt * 8 + 2 * lc;
            if (HALF_OUT) {
                __half* C = (__half*)Cv;
                *(__half2*)&C[(size_t)row * N + col] =
                    __floats2half2_rn(acc[mt][nt][0], acc[mt][nt][1]);
                *(__half2*)&C[(size_t)(row + 8) * N + col] =
                    __floats2half2_rn(acc[mt][nt][2], acc[mt][nt][3]);
            } else {
                float* C = (float*)Cv;
                *(float2*)&C[(size_t)row * N + col] =
                    make_float2(acc[mt][nt][0], acc[mt][nt][1]);
                *(float2*)&C[(size_t)(row + 8) * N + col] =
                    make_float2(acc[mt][nt][2], acc[mt][nt][3]);
            }
        }
    }
}

// =================================================================
// pre-pass kernels
// =================================================================
__global__ __launch_bounds__(256) void to_half_kernel(
    const float* __restrict__ in, __half* __restrict__ out, int n4)
{
    int i = blockIdx.x * blockDim.x + threadIdx.x;
    int stride = gridDim.x * blockDim.x;
    for (; i < n4; i += stride) {
        float4 v = ((const float4*)in)[i];
        __half2 h0 = __floats2half2_rn(v.x, v.y);
        __half2 h1 = __floats2half2_rn(v.z, v.w);
        ((uint2*)out)[i] = make_uint2(h2bits(h0), h2bits(h1));
    }
}

__global__ __launch_bounds__(256) void transpose_half_kernel(
    const float* __restrict__ W, __half* __restrict__ WT, int K, int N)
{
    __shared__ float s[32][33];
    const int tid = threadIdx.x;
    const int k0 = blockIdx.y * 32;
    const int n0 = blockIdx.x * 32;
    {
        int rk = tid >> 3;
        int cn = tid & 7;
        float4 v = *(const float4*)&W[(size_t)(k0 + rk) * N + n0 + cn * 4];
        s[rk][cn*4+0] = v.x; s[rk][cn*4+1] = v.y;
        s[rk][cn*4+2] = v.z; s[rk][cn*4+3] = v.w;
    }
    __syncthreads();
    {
        int rn = tid >> 3;
        int ck = tid & 7;
        __half2 h0 = __floats2half2_rn(s[ck*4+0][rn], s[ck*4+1][rn]);
        __half2 h1 = __floats2half2_rn(s[ck*4+2][rn], s[ck*4+3][rn]);
        *(uint2*)&WT[(size_t)(n0 + rn) * K + k0 + ck * 4] =
            make_uint2(h2bits(h0), h2bits(h1));
    }
}

// =================================================================
// QK-RMSNorm + RoPE, warp-per-head (no block syncs in head loop).
// RoPE partner d <-> d+64 maps to same lane (j <-> j^2 offsets).
// =================================================================
__global__ __launch_bounds__(128) void norm_rope_kernel(
    const float* __restrict__ qin, const float* __restrict__ kin,
    __half* __restrict__ qout, __half* __restrict__ kout,
    const float* __restrict__ q_scale, const float* __restrict__ k_scale,
    const int* __restrict__ positions)
{
    const int n = blockIdx.x;
    const int tid = threadIdx.x;
    const int w = tid >> 5, lane = tid & 31;
    __shared__ float cs[128], sn[128], sq[128], sk[128];

    if (tid < 64) {
        double invf = exp2(-(double)tid * (13.287712379549449 / 64.0));
        double ang  = (double)positions[n] * invf;
        const double twopi = 6.283185307179586476925287;
        ang -= twopi * floor(ang / twopi);
        float af = (float)ang;
        float c, s;
        sincosf(af, &s, &c);
        cs[tid] = c;       sn[tid] = s;
        cs[tid + 64] = c;  sn[tid + 64] = s;
    }
    sq[tid] = q_scale[tid];
    sk[tid] = k_scale[tid];
    __syncthreads();

    for (int hi = w; hi < NUM_HEADS + NUM_KV; hi += 4) {
        const float* vec;
        __half* vecout;
        const float* sc;
        if (hi < NUM_HEADS) {
            vec    = qin  + ((size_t)n * NUM_HEADS + hi) * HEAD_DIM;
            vecout = qout + ((size_t)n * NUM_HEADS + hi) * HEAD_DIM;
            sc = sq;
        } else {
            vec    = kin  + ((size_t)n * NUM_KV + (hi - NUM_HEADS)) * HEAD_DIM;
            vecout = kout + ((size_t)n * NUM_KV + (hi - NUM_HEADS)) * HEAD_DIM;
            sc = sk;
        }
        float val[4];
#pragma unroll
        for (int j = 0; j < 4; ++j) val[j] = vec[lane + 32 * j];
        float ss = val[0]*val[0] + val[1]*val[1] + val[2]*val[2] + val[3]*val[3];
#pragma unroll
        for (int o = 16; o > 0; o >>= 1) ss += __shfl_xor_sync(0xffffffffu, ss, o);
        float rinv = rsqrtf(ss * (1.0f / HEAD_DIM) + 1e-6f);
        float nv[4];
#pragma unroll
        for (int j = 0; j < 4; ++j) nv[j] = val[j] * rinv * sc[lane + 32 * j];
#pragma unroll
        for (int j = 0; j < 4; ++j) {
            int d = lane + 32 * j;
            float rot = (j < 2) ? -nv[j + 2] : nv[j - 2];
            vecout[d] = __float2half_rn(fmaf(nv[j], cs[d], rot * sn[d]));
        }
    }
}

// =================================================================
// Flash attention fp16, BM=128, BN=64, 256 threads (8 warps).
// cp.async double-buffered K and V; prefetch distance = 1 iter.
// =================================================================
#define FST 136
#define PST 72
// halves offsets
#define FO_Q  0
#define FO_K0 17408
#define FO_K1 26112
#define FO_V0 34816
#define FO_V1 43520
#define FO_P  52224
#define FLASH_SMEM ((52224 + 128*PST) * 2)   // 122880 B

__global__ __launch_bounds__(256, 1) void flash_f16_kernel(
    const __half* __restrict__ Qh, const __half* __restrict__ Kh,
    const __half* __restrict__ Vh, __half* __restrict__ Oh)
{
    extern __shared__ __half fsm[];
    const uint32_t sb = smem_u32(fsm);
    __half* Qs = fsm + FO_Q;
    __half* Ps = fsm + FO_P;

    const int tid  = threadIdx.x;
    const int lane = tid & 31;
    const int w    = tid >> 5;
    const int lg   = lane >> 2;
    const int lc   = lane & 3;
    const int h    = blockIdx.y;
    const int kvh  = h >> 2;
    const int qt   = gridDim.x - 1 - blockIdx.x;   // heavy tiles first
    const int m0   = qt * 128;
    const int ntmax = 2 * qt + 1;
    const float softscale = 0.08838834764831845f;

    const int ctok = tid >> 4;        // 0..15 base for cp loops
    const int cu   = tid & 15;

    // ---- issue K0/V0 prefetch (group 0) ----
    {
        uint32_t kd = sb + FO_K0 * 2;
        uint32_t vd = sb + FO_V0 * 2;
#pragma unroll
        for (int it = 0; it < 4; ++it) {
            int tok = ctok + it * 16;
            const __half* ks = Kh + ((size_t)tok * NUM_KV + kvh) * HEAD_DIM + cu * 8;
            const __half* vs = Vh + ((size_t)tok * NUM_KV + kvh) * HEAD_DIM + cu * 8;
            cp16(kd + tok * 272 + cu * 16, ks);
            cp16(vd + tok * 272 + cu * 16, vs);
        }
        CP_COMMIT();
    }

    // ---- load Q tile (128 x 128 halves) with regular loads ----
#pragma unroll
    for (int it = 0; it < 8; ++it) {
        int id  = tid + it * 256;
        int tok = id >> 4;
        int u   = id & 15;
        *(uint4*)&Qs[tok * FST + u * 8] =
            *(const uint4*)&Qh[((size_t)(m0 + tok) * NUM_HEADS + h) * HEAD_DIM + u * 8];
    }

    float o[16][4];
#pragma unroll
    for (int dt = 0; dt < 16; ++dt)
#pragma unroll
        for (int e = 0; e < 4; ++e) o[dt][e] = 0.f;
    float mrun[2] = {-1e30f, -1e30f};
    float lrun[2] = {0.f, 0.f};

    for (int nt = 0; nt <= ntmax; ++nt) {
        const int n0 = nt * 64;
        const uint32_t kbuf = sb + (((nt & 1) ? FO_K1 : FO_K0)) * 2;
        const uint32_t vbuf = sb + (((nt & 1) ? FO_V1 : FO_V0)) * 2;

        __syncthreads();   // close iteration nt-1 entirely
        // ---- prefetch K/V for nt+1 into the other buffers ----
        if (nt + 1 <= ntmax) {
            const int pn0 = (nt + 1) * 64;
            uint32_t kd = sb + ((((nt + 1) & 1) ? FO_K1 : FO_K0)) * 2;
            uint32_t vd = sb + ((((nt + 1) & 1) ? FO_V1 : FO_V0)) * 2;
#pragma unroll
            for (int it = 0; it < 4; ++it) {
                int tok = ctok + it * 16;
                const __half* ks = Kh + ((size_t)(pn0 + tok) * NUM_KV + kvh) * HEAD_DIM + cu * 8;
                const __half* vs = Vh + ((size_t)(pn0 + tok) * NUM_KV + kvh) * HEAD_DIM + cu * 8;
                cp16(kd + tok * 272 + cu * 16, ks);
                cp16(vd + tok * 272 + cu * 16, vs);
            }
        }
        CP_COMMIT();
        CP_WAIT1();        // group nt complete (nt+1 may stay in flight)
        __syncthreads();   // K/V[nt] visible to all warps; Q visible (first iter)

        // ---- S = Q K^T ----
        const __half* Kb = (const __half*)fsm + ((nt & 1) ? FO_K1 : FO_K0);
        float s[8][4];
#pragma unroll
        for (int n = 0; n < 8; ++n)
#pragma unroll
            for (int e = 0; e < 4; ++e) s[n][e] = 0.f;

#pragma unroll
        for (int ks = 0; ks < 8; ++ks) {
            const __half* qp = Qs + (w * 16 + lg) * FST + ks * 16 + 2 * lc;
            uint32_t af[4];
            af[0] = ldu32(qp);
            af[1] = ldu32(qp + 8 * FST);
            af[2] = ldu32(qp + 8);
            af[3] = ldu32(qp + 8 * FST + 8);
#pragma unroll
            for (int n = 0; n < 8; ++n) {
                const __half* kp = Kb + (n * 8 + lg) * FST + ks * 16 + 2 * lc;
                mma16(s[n], af, ldu32(kp), ldu32(kp + 8));
            }
        }

        // ---- softmax update ----
        const bool diag = (nt >= 2 * qt);   // only last two iters need masking
        float pmax[2] = {-1e30f, -1e30f};
#pragma unroll
        for (int n = 0; n < 8; ++n) {
#pragma unroll
            for (int e = 0; e < 4; ++e) {
                float v = s[n][e] * softscale;
                if (diag) {
                    int row = m0 + w * 16 + lg + (e >> 1) * 8;
                    int col = n0 + n * 8 + 2 * lc + (e & 1);
                    if (col > row) v = -1e30f;
                }
                s[n][e] = v;
                pmax[e >> 1] = fmaxf(pmax[e >> 1], v);
            }
        }
#pragma unroll
        for (int half = 0; half < 2; ++half) {
            pmax[half] = fmaxf(pmax[half], __shfl_xor_sync(0xffffffffu, pmax[half], 1));
            pmax[half] = fmaxf(pmax[half], __shfl_xor_sync(0xffffffffu, pmax[half], 2));
        }
        float alpha[2];
#pragma unroll
        for (int half = 0; half < 2; ++half) {
            float nm = fmaxf(mrun[half], pmax[half]);
            alpha[half] = __expf(mrun[half] - nm);
            mrun[half] = nm;
            lrun[half] *= alpha[half];
        }
#pragma unroll
        for (int dt = 0; dt < 16; ++dt) {
            o[dt][0] *= alpha[0]; o[dt][1] *= alpha[0];
            o[dt][2] *= alpha[1]; o[dt][3] *= alpha[1];
        }
        float lsum[2] = {0.f, 0.f};
#pragma unroll
        for (int n = 0; n < 8; ++n) {
            float p0 = __expf(s[n][0] - mrun[0]);
            float p1 = __expf(s[n][1] - mrun[0]);
            float p2 = __expf(s[n][2] - mrun[1]);
            float p3 = __expf(s[n][3] - mrun[1]);
            lsum[0] += p0 + p1;
            lsum[1] += p2 + p3;
            *(__half2*)&Ps[(w * 16 + lg) * PST + n * 8 + 2 * lc] =
                __floats2half2_rn(p0, p1);
            *(__half2*)&Ps[(w * 16 + lg + 8) * PST + n * 8 + 2 * lc] =
                __floats2half2_rn(p2, p3);
        }
#pragma unroll
        for (int half = 0; half < 2; ++half) {
            lsum[half] += __shfl_xor_sync(0xffffffffu, lsum[half], 1);
            lsum[half] += __shfl_xor_sync(0xffffffffu, lsum[half], 2);
            lrun[half] += lsum[half];
        }
        __syncthreads();   // P visible to all warps

        // ---- O += P V (V B-frag via ldmatrix.x2.trans) ----
#pragma unroll
        for (int ks = 0; ks < 4; ++ks) {
            const __half* pp = Ps + (w * 16 + lg) * PST + ks * 16 + 2 * lc;
            uint32_t af[4];
            af[0] = ldu32(pp);
            af[1] = ldu32(pp + 8 * PST);
            af[2] = ldu32(pp + 8);
            af[3] = ldu32(pp + 8 * PST + 8);
            uint32_t vrow = vbuf + ((uint32_t)(ks * 16 + (lane & 15))) * 272;
#pragma unroll
            for (int dt = 0; dt < 16; ++dt) {
                uint32_t r0, r1;
                asm volatile(
                    "ldmatrix.sync.aligned.m8n8.x2.trans.shared.b16 {%0,%1}, [%2];"
                    : "=r"(r0), "=r"(r1) : "r"(vrow + dt * 16));
                mma16(o[dt], af, r0, r1);
            }
        }
    }

    // ---- finalize ----
    float inv0 = 1.f / lrun[0];
    float inv1 = 1.f / lrun[1];
#pragma unroll
    for (int dt = 0; dt < 16; ++dt) {
        int row = m0 + w * 16 + lg;
        int col = dt * 8 + 2 * lc;
        *(__half2*)&Oh[((size_t)row * NUM_HEADS + h) * HEAD_DIM + col] =
            __floats2half2_rn(o[dt][0] * inv0, o[dt][1] * inv0);
        *(__half2*)&Oh[((size_t)(row + 8) * NUM_HEADS + h) * HEAD_DIM + col] =
            __floats2half2_rn(o[dt][2] * inv1, o[dt][3] * inv1);
    }
}

// =================================================================
// kernel_launch
// =================================================================
extern "C" void kernel_launch(void* const* d_in, const int* in_sizes, int n_in,
                              void* d_out, int out_size)
{
    const float* x   = (const float*)d_in[0];
    const int*   pos = (const int*)  d_in[1];
    const float* Wq  = (const float*)d_in[2];
    const float* Wk  = (const float*)d_in[3];
    const float* Wv  = (const float*)d_in[4];
    const float* Wo  = (const float*)d_in[5];
    const float* qsc = (const float*)d_in[6];
    const float* ksc = (const float*)d_in[7];
    float* out = (float*)d_out;

    float *gq, *gk;
    __half *gqh, *gkh, *gvh, *gctxh, *gxh, *gwqT, *gwkT, *gwvT, *gwoT;
    cudaGetSymbolAddress((void**)&gq,    g_q);
    cudaGetSymbolAddress((void**)&gk,    g_k);
    cudaGetSymbolAddress((void**)&gqh,   g_qh);
    cudaGetSymbolAddress((void**)&gkh,   g_kh);
    cudaGetSymbolAddress((void**)&gvh,   g_vh);
    cudaGetSymbolAddress((void**)&gctxh, g_ctxh);
    cudaGetSymbolAddress((void**)&gxh,   g_xh);
    cudaGetSymbolAddress((void**)&gwqT,  g_wqT);
    cudaGetSymbolAddress((void**)&gwkT,  g_wkT);
    cudaGetSymbolAddress((void**)&gwvT,  g_wvT);
    cudaGetSymbolAddress((void**)&gwoT,  g_woT);

    const int NQ = NUM_HEADS * HEAD_DIM;   // 4096
    const int NK = NUM_KV * HEAD_DIM;      // 1024

    cudaFuncSetAttribute(gemm_f16<false>,
                         cudaFuncAttributeMaxDynamicSharedMemorySize, GEMM_SMEM);
    cudaFuncSetAttribute(gemm_f16<true>,
                         cudaFuncAttributeMaxDynamicSharedMemorySize, GEMM_SMEM);
    cudaFuncSetAttribute(flash_f16_kernel,
                         cudaFuncAttributeMaxDynamicSharedMemorySize, FLASH_SMEM);

    // ---- pre-pass ----
    to_half_kernel<<<1024, 256>>>(x, gxh, (SEQ * D_IN) / 4);
    transpose_half_kernel<<<dim3(NQ / 32, D_IN / 32), 256>>>(Wq, gwqT, D_IN, NQ);
    transpose_half_kernel<<<dim3(NK / 32, D_IN / 32), 256>>>(Wk, gwkT, D_IN, NK);
    transpose_half_kernel<<<dim3(NK / 32, D_IN / 32), 256>>>(Wv, gwvT, D_IN, NK);
    transpose_half_kernel<<<dim3(D_IN / 32, NQ / 32), 256>>>(Wo, gwoT, NQ, D_IN);

    // ---- QKV projections ----
    gemm_f16<false><<<dim3(NQ / 128, SEQ / 128), 256, GEMM_SMEM>>>(
        gxh, gwqT, gq, SEQ, NQ, D_IN);
    gemm_f16<false><<<dim3(NK / 128, SEQ / 128), 256, GEMM_SMEM>>>(
        gxh, gwkT, gk, SEQ, NK, D_IN);
    gemm_f16<true><<<dim3(NK / 128, SEQ / 128), 256, GEMM_SMEM>>>(
        gxh, gwvT, gvh, SEQ, NK, D_IN);

    // ---- RMSNorm + RoPE ----
    norm_rope_kernel<<<SEQ, 128>>>(gq, gk, gqh, gkh, qsc, ksc, pos);

    // ---- Flash attention (BM=128, pipelined) ----
    flash_f16_kernel<<<dim3(SEQ / 128, NUM_HEADS), 256, FLASH_SMEM>>>(
        gqh, gkh, gvh, gctxh);

    // ---- Output projection ----
    gemm_f16<false><<<dim3(D_IN / 128, SEQ / 128), 256, GEMM_SMEM>>>(
        gctxh, gwoT, out, SEQ, D_IN, NQ);
}

// round 6
// speedup vs baseline: 7.9990x; 1.0979x over previous
#include <cuda_runtime.h>
#include <cuda_fp16.h>
#include <math.h>
#include <stdint.h>

#define D_IN       4096
#define NUM_HEADS  32
#define HEAD_DIM   128
#define NUM_KV     8
#define SEQ        2048

// -------- scratch (device globals; no allocation allowed) --------
__device__ float  g_q  [(size_t)SEQ * NUM_HEADS * HEAD_DIM];
__device__ float  g_k  [(size_t)SEQ * NUM_KV   * HEAD_DIM];
__device__ __half g_qh [(size_t)SEQ * NUM_HEADS * HEAD_DIM];
__device__ __half g_kh [(size_t)SEQ * NUM_KV   * HEAD_DIM];
__device__ __half g_vh [(size_t)SEQ * NUM_KV   * HEAD_DIM];
__device__ __half g_ctxh[(size_t)SEQ * NUM_HEADS * HEAD_DIM];
__device__ __half g_xh [(size_t)SEQ * D_IN];
__device__ __half g_wqkvT[(size_t)6144 * D_IN];                 // [Wq^T|Wk^T|Wv^T]
__device__ __half g_woT[(size_t)D_IN * (NUM_HEADS*HEAD_DIM)];

// ---------------- helpers ----------------
__device__ __forceinline__ uint32_t smem_u32(const void* p) {
    uint32_t a;
    asm("{ .reg .u64 t; cvta.to.shared.u64 t, %1; cvt.u32.u64 %0, t; }"
        : "=r"(a) : "l"(p));
    return a;
}
__device__ __forceinline__ void cp16(uint32_t d, const void* s) {
    asm volatile("cp.async.cg.shared.global [%0], [%1], 16;"
                 :: "r"(d), "l"(s) : "memory");
}
#define CP_COMMIT() asm volatile("cp.async.commit_group;" ::: "memory")
#define CP_WAIT1()  asm volatile("cp.async.wait_group 1;" ::: "memory")

__device__ __forceinline__ void mma16(float* c, const uint32_t* a,
                                      uint32_t b0, uint32_t b1) {
    asm volatile(
        "mma.sync.aligned.m16n8k16.row.col.f32.f16.f16.f32 "
        "{%0,%1,%2,%3},{%4,%5,%6,%7},{%8,%9},{%0,%1,%2,%3};\n"
        : "+f"(c[0]), "+f"(c[1]), "+f"(c[2]), "+f"(c[3])
        : "r"(a[0]), "r"(a[1]), "r"(a[2]), "r"(a[3]), "r"(b0), "r"(b1));
}
__device__ __forceinline__ void ldsm4(uint32_t addr, uint32_t& r0, uint32_t& r1,
                                      uint32_t& r2, uint32_t& r3) {
    asm volatile("ldmatrix.sync.aligned.m8n8.x4.shared.b16 {%0,%1,%2,%3}, [%4];"
                 : "=r"(r0), "=r"(r1), "=r"(r2), "=r"(r3) : "r"(addr));
}
__device__ __forceinline__ uint32_t h2bits(__half2 h) {
    return *(uint32_t*)&h;
}

// =================================================================
// fp16 GEMM with region-routing epilogue.
// C[M,N] = A[M,K] @ Bt^T. BM=BN=128, BK=64, 256 thr, 3-stage
// cp.async, ldmatrix fragments, 2 CTAs/SM.
// cols [0,nq_end)      -> Cq fp32, ld ldq
// cols [nq_end,nk_end) -> Ck fp32, ld 1024
// cols [nk_end,N)      -> Cv fp16, ld 1024
// =================================================================
#define GSTAGE_BYTES 36864
#define GEMM_SMEM (3 * GSTAGE_BYTES)

__global__ __launch_bounds__(256, 2) void gemm_f16(
    const __half* __restrict__ A, const __half* __restrict__ B,
    float* __restrict__ Cq, float* __restrict__ Ck, __half* __restrict__ Cv,
    int ldq, int nq_end, int nk_end, int N, int K)
{
    extern __shared__ __half sh[];
    const uint32_t sb = smem_u32(sh);
    const int tid = threadIdx.x;
    const int lane = tid & 31, wid = tid >> 5;
    const int wm = wid & 3, wn = wid >> 2;
    const int lg = lane >> 2, lc = lane & 3;
    const int m0 = blockIdx.y * 128, n0 = blockIdx.x * 128;
    const int nsteps = K / 64;
    const int lrow = tid >> 3;
    const int lchk = tid & 7;

    const uint32_t a_off = (uint32_t)((wm * 32 + (lane & 15)) * 144 + (lane >> 4) * 16);
    const uint32_t b_off = (uint32_t)(18432 +
        (wn * 64 + (lane & 7) + ((lane >> 4) * 8)) * 144 + ((lane >> 3) & 1) * 16);

    float acc[2][8][4];
#pragma unroll
    for (int i = 0; i < 2; ++i)
#pragma unroll
        for (int j = 0; j < 8; ++j)
#pragma unroll
            for (int e = 0; e < 4; ++e) acc[i][j][e] = 0.f;

    const __half* Ag = A + (size_t)m0 * K;
    const __half* Bg = B + (size_t)n0 * K;

#define LOAD_STAGE(s, k0) do {                                            \
    uint32_t as_ = sb + (uint32_t)(s) * GSTAGE_BYTES;                     \
    uint32_t bs_ = as_ + 18432;                                           \
    _Pragma("unroll")                                                     \
    for (int j_ = 0; j_ < 4; ++j_) {                                      \
        int row_ = lrow + 32 * j_;                                        \
        cp16(as_ + row_ * 144 + lchk * 16,                                \
             Ag + (size_t)row_ * K + (k0) + lchk * 8);                    \
        cp16(bs_ + row_ * 144 + lchk * 16,                                \
             Bg + (size_t)row_ * K + (k0) + lchk * 8);                    \
    }                                                                     \
} while (0)

    LOAD_STAGE(0, 0);  CP_COMMIT();
    LOAD_STAGE(1, 64); CP_COMMIT();

    for (int s = 0; s < nsteps; ++s) {
        CP_WAIT1();
        __syncthreads();
        if (s + 2 < nsteps) {
            int sn = s + 2; int bufn = sn - (sn / 3) * 3;
            LOAD_STAGE(bufn, sn * 64);
        }
        CP_COMMIT();

        const int buf = s - (s / 3) * 3;
        const uint32_t st = sb + (uint32_t)buf * GSTAGE_BYTES;
#pragma unroll
        for (int ks = 0; ks < 4; ++ks) {
            uint32_t af[2][4];
            ldsm4(st + a_off + ks * 32,            af[0][0], af[0][1], af[0][2], af[0][3]);
            ldsm4(st + a_off + ks * 32 + 16 * 144, af[1][0], af[1][1], af[1][2], af[1][3]);
            uint32_t bf[8][2];
#pragma unroll
            for (int ntp = 0; ntp < 4; ++ntp) {
                uint32_t r0, r1, r2, r3;
                ldsm4(st + b_off + ks * 32 + ntp * 16 * 144, r0, r1, r2, r3);
                bf[2*ntp][0] = r0; bf[2*ntp][1] = r1;
                bf[2*ntp+1][0] = r2; bf[2*ntp+1][1] = r3;
            }
#pragma unroll
            for (int nt = 0; nt < 8; ++nt) {
                mma16(acc[0][nt], af[0], bf[nt][0], bf[nt][1]);
                mma16(acc[1][nt], af[1], bf[nt][0], bf[nt][1]);
            }
        }
    }
#undef LOAD_STAGE

    // region-routing epilogue (whole 128-col block is in one region)
    if (n0 < nq_end) {
#pragma unroll
        for (int mt = 0; mt < 2; ++mt)
#pragma unroll
            for (int nt = 0; nt < 8; ++nt) {
                int row = m0 + wm * 32 + mt * 16 + lg;
                int col = n0 + wn * 64 + nt * 8 + 2 * lc;
                *(float2*)&Cq[(size_t)row * ldq + col] =
                    make_float2(acc[mt][nt][0], acc[mt][nt][1]);
                *(float2*)&Cq[(size_t)(row + 8) * ldq + col] =
                    make_float2(acc[mt][nt][2], acc[mt][nt][3]);
            }
    } else if (n0 < nk_end) {
#pragma unroll
        for (int mt = 0; mt < 2; ++mt)
#pragma unroll
            for (int nt = 0; nt < 8; ++nt) {
                int row = m0 + wm * 32 + mt * 16 + lg;
                int col = n0 - nq_end + wn * 64 + nt * 8 + 2 * lc;
                *(float2*)&Ck[(size_t)row * 1024 + col] =
                    make_float2(acc[mt][nt][0], acc[mt][nt][1]);
                *(float2*)&Ck[(size_t)(row + 8) * 1024 + col] =
                    make_float2(acc[mt][nt][2], acc[mt][nt][3]);
            }
    } else {
#pragma unroll
        for (int mt = 0; mt < 2; ++mt)
#pragma unroll
            for (int nt = 0; nt < 8; ++nt) {
                int row = m0 + wm * 32 + mt * 16 + lg;
                int col = n0 - nk_end + wn * 64 + nt * 8 + 2 * lc;
                *(__half2*)&Cv[(size_t)row * 1024 + col] =
                    __floats2half2_rn(acc[mt][nt][0], acc[mt][nt][1]);
                *(__half2*)&Cv[(size_t)(row + 8) * 1024 + col] =
                    __floats2half2_rn(acc[mt][nt][2], acc[mt][nt][3]);
            }
    }
}

// =================================================================
// pre-pass kernels
// =================================================================
__global__ __launch_bounds__(256) void to_half_kernel(
    const float* __restrict__ in, __half* __restrict__ out, int n4)
{
    int i = blockIdx.x * blockDim.x + threadIdx.x;
    int stride = gridDim.x * blockDim.x;
    for (; i < n4; i += stride) {
        float4 v = ((const float4*)in)[i];
        __half2 h0 = __floats2half2_rn(v.x, v.y);
        __half2 h1 = __floats2half2_rn(v.z, v.w);
        ((uint2*)out)[i] = make_uint2(h2bits(h0), h2bits(h1));
    }
}

__global__ __launch_bounds__(256) void transpose_half_kernel(
    const float* __restrict__ W, __half* __restrict__ WT, int K, int N)
{
    __shared__ float s[32][33];
    const int tid = threadIdx.x;
    const int k0 = blockIdx.y * 32;
    const int n0 = blockIdx.x * 32;
    {
        int rk = tid >> 3;
        int cn = tid & 7;
        float4 v = *(const float4*)&W[(size_t)(k0 + rk) * N + n0 + cn * 4];
        s[rk][cn*4+0] = v.x; s[rk][cn*4+1] = v.y;
        s[rk][cn*4+2] = v.z; s[rk][cn*4+3] = v.w;
    }
    __syncthreads();
    {
        int rn = tid >> 3;
        int ck = tid & 7;
        __half2 h0 = __floats2half2_rn(s[ck*4+0][rn], s[ck*4+1][rn]);
        __half2 h1 = __floats2half2_rn(s[ck*4+2][rn], s[ck*4+3][rn]);
        *(uint2*)&WT[(size_t)(n0 + rn) * K + k0 + ck * 4] =
            make_uint2(h2bits(h0), h2bits(h1));
    }
}

// =================================================================
// QK-RMSNorm + RoPE, warp-per-head.
// =================================================================
__global__ __launch_bounds__(128) void norm_rope_kernel(
    const float* __restrict__ qin, const float* __restrict__ kin,
    __half* __restrict__ qout, __half* __restrict__ kout,
    const float* __restrict__ q_scale, const float* __restrict__ k_scale,
    const int* __restrict__ positions)
{
    const int n = blockIdx.x;
    const int tid = threadIdx.x;
    const int w = tid >> 5, lane = tid & 31;
    __shared__ float cs[128], sn[128], sq[128], sk[128];

    if (tid < 64) {
        double invf = exp2(-(double)tid * (13.287712379549449 / 64.0));
        double ang  = (double)positions[n] * invf;
        const double twopi = 6.283185307179586476925287;
        ang -= twopi * floor(ang / twopi);
        float af = (float)ang;
        float c, s;
        sincosf(af, &s, &c);
        cs[tid] = c;       sn[tid] = s;
        cs[tid + 64] = c;  sn[tid + 64] = s;
    }
    sq[tid] = q_scale[tid];
    sk[tid] = k_scale[tid];
    __syncthreads();

    for (int hi = w; hi < NUM_HEADS + NUM_KV; hi += 4) {
        const float* vec;
        __half* vecout;
        const float* sc;
        if (hi < NUM_HEADS) {
            vec    = qin  + ((size_t)n * NUM_HEADS + hi) * HEAD_DIM;
            vecout = qout + ((size_t)n * NUM_HEADS + hi) * HEAD_DIM;
            sc = sq;
        } else {
            vec    = kin  + ((size_t)n * NUM_KV + (hi - NUM_HEADS)) * HEAD_DIM;
            vecout = kout + ((size_t)n * NUM_KV + (hi - NUM_HEADS)) * HEAD_DIM;
            sc = sk;
        }
        float val[4];
#pragma unroll
        for (int j = 0; j < 4; ++j) val[j] = vec[lane + 32 * j];
        float ss = val[0]*val[0] + val[1]*val[1] + val[2]*val[2] + val[3]*val[3];
#pragma unroll
        for (int o = 16; o > 0; o >>= 1) ss += __shfl_xor_sync(0xffffffffu, ss, o);
        float rinv = rsqrtf(ss * (1.0f / HEAD_DIM) + 1e-6f);
        float nv[4];
#pragma unroll
        for (int j = 0; j < 4; ++j) nv[j] = val[j] * rinv * sc[lane + 32 * j];
#pragma unroll
        for (int j = 0; j < 4; ++j) {
            int d = lane + 32 * j;
            float rot = (j < 2) ? -nv[j + 2] : nv[j - 2];
            vecout[d] = __float2half_rn(fmaf(nv[j], cs[d], rot * sn[d]));
        }
    }
}

// =================================================================
// Flash attention fp16, BM=128, BN=64, 256 threads.
// cp.async double-buffered K/V; Q/K frags via ldmatrix.x4;
// P kept in registers (S accum layout == PV A-frag layout).
// =================================================================
#define FST 136     // halves; 272 bytes
// halves offsets
#define FO_Q  0
#define FO_K0 17408
#define FO_K1 26112
#define FO_V0 34816
#define FO_V1 43520
#define FLASH_SMEM (52224 * 2)   // 104448 B

__global__ __launch_bounds__(256, 1) void flash_f16_kernel(
    const __half* __restrict__ Qh, const __half* __restrict__ Kh,
    const __half* __restrict__ Vh, __half* __restrict__ Oh)
{
    extern __shared__ __half fsm[];
    const uint32_t sb = smem_u32(fsm);
    __half* Qs = fsm + FO_Q;

    const int tid  = threadIdx.x;
    const int lane = tid & 31;
    const int w    = tid >> 5;
    const int lg   = lane >> 2;
    const int lc   = lane & 3;
    const int h    = blockIdx.y;
    const int kvh  = h >> 2;
    const int qt   = gridDim.x - 1 - blockIdx.x;   // heavy tiles first
    const int m0   = qt * 128;
    const int ntmax = 2 * qt + 1;
    const float softscale = 0.08838834764831845f;

    const int ctok = tid >> 4;
    const int cu   = tid & 15;

    // ldmatrix lane offsets
    const int m_sel = lane >> 3;      // 0..3
    const int r_sel = lane & 7;
    const uint32_t q_lane = sb + (uint32_t)((w * 16 + (m_sel & 1) * 8 + r_sel) * 272
                                            + (m_sel >> 1) * 16);
    const uint32_t k_lane_off = (uint32_t)(((m_sel >> 1) * 8 + r_sel) * 272
                                           + (m_sel & 1) * 16);

    // ---- issue K0/V0 prefetch ----
    {
        uint32_t kd = sb + FO_K0 * 2;
        uint32_t vd = sb + FO_V0 * 2;
#pragma unroll
        for (int it = 0; it < 4; ++it) {
            int tok = ctok + it * 16;
            cp16(kd + tok * 272 + cu * 16,
                 Kh + ((size_t)tok * NUM_KV + kvh) * HEAD_DIM + cu * 8);
            cp16(vd + tok * 272 + cu * 16,
                 Vh + ((size_t)tok * NUM_KV + kvh) * HEAD_DIM + cu * 8);
        }
        CP_COMMIT();
    }

    // ---- load Q tile ----
#pragma unroll
    for (int it = 0; it < 8; ++it) {
        int id  = tid + it * 256;
        int tok = id >> 4;
        int u   = id & 15;
        *(uint4*)&Qs[tok * FST + u * 8] =
            *(const uint4*)&Qh[((size_t)(m0 + tok) * NUM_HEADS + h) * HEAD_DIM + u * 8];
    }

    float o[16][4];
#pragma unroll
    for (int dt = 0; dt < 16; ++dt)
#pragma unroll
        for (int e = 0; e < 4; ++e) o[dt][e] = 0.f;
    float mrun[2] = {-1e30f, -1e30f};
    float lrun[2] = {0.f, 0.f};

    for (int nt = 0; nt <= ntmax; ++nt) {
        const int n0 = nt * 64;
        const uint32_t kbuf = sb + (((nt & 1) ? FO_K1 : FO_K0)) * 2;
        const uint32_t vbuf = sb + (((nt & 1) ? FO_V1 : FO_V0)) * 2;

        __syncthreads();   // close iteration nt-1 (its buffers now reusable)
        if (nt + 1 <= ntmax) {
            const int pn0 = (nt + 1) * 64;
            uint32_t kd = sb + ((((nt + 1) & 1) ? FO_K1 : FO_K0)) * 2;
            uint32_t vd = sb + ((((nt + 1) & 1) ? FO_V1 : FO_V0)) * 2;
#pragma unroll
            for (int it = 0; it < 4; ++it) {
                int tok = ctok + it * 16;
                cp16(kd + tok * 272 + cu * 16,
                     Kh + ((size_t)(pn0 + tok) * NUM_KV + kvh) * HEAD_DIM + cu * 8);
                cp16(vd + tok * 272 + cu * 16,
                     Vh + ((size_t)(pn0 + tok) * NUM_KV + kvh) * HEAD_DIM + cu * 8);
            }
        }
        CP_COMMIT();
        CP_WAIT1();
        __syncthreads();   // K/V[nt] visible to all warps

        // ---- S = Q K^T (ldmatrix.x4 frags) ----
        float s[8][4];
#pragma unroll
        for (int n = 0; n < 8; ++n)
#pragma unroll
            for (int e = 0; e < 4; ++e) s[n][e] = 0.f;

        const uint32_t k_lane = kbuf + k_lane_off;
#pragma unroll
        for (int ks = 0; ks < 8; ++ks) {
            uint32_t af[4];
            ldsm4(q_lane + ks * 32, af[0], af[1], af[2], af[3]);
#pragma unroll
            for (int np = 0; np < 4; ++np) {
                uint32_t r0, r1, r2, r3;
                ldsm4(k_lane + np * 16 * 272 + ks * 32, r0, r1, r2, r3);
                mma16(s[2*np],   af, r0, r1);
                mma16(s[2*np+1], af, r2, r3);
            }
        }

        // ---- softmax update ----
        const bool diag = (nt >= 2 * qt);
        float pmax[2] = {-1e30f, -1e30f};
#pragma unroll
        for (int n = 0; n < 8; ++n) {
#pragma unroll
            for (int e = 0; e < 4; ++e) {
                float v = s[n][e] * softscale;
                if (diag) {
                    int row = m0 + w * 16 + lg + (e >> 1) * 8;
                    int col = n0 + n * 8 + 2 * lc + (e & 1);
                    if (col > row) v = -1e30f;
                }
                s[n][e] = v;
                pmax[e >> 1] = fmaxf(pmax[e >> 1], v);
            }
        }
#pragma unroll
        for (int half = 0; half < 2; ++half) {
            pmax[half] = fmaxf(pmax[half], __shfl_xor_sync(0xffffffffu, pmax[half], 1));
            pmax[half] = fmaxf(pmax[half], __shfl_xor_sync(0xffffffffu, pmax[half], 2));
        }
        float alpha[2];
#pragma unroll
        for (int half = 0; half < 2; ++half) {
            float nm = fmaxf(mrun[half], pmax[half]);
            alpha[half] = __expf(mrun[half] - nm);
            mrun[half] = nm;
            lrun[half] *= alpha[half];
        }
#pragma unroll
        for (int dt = 0; dt < 16; ++dt) {
            o[dt][0] *= alpha[0]; o[dt][1] *= alpha[0];
            o[dt][2] *= alpha[1]; o[dt][3] *= alpha[1];
        }
        // P = exp(S - m), packed in registers (PV A-frag layout)
        uint32_t pf[8][2];
        float lsum[2] = {0.f, 0.f};
#pragma unroll
        for (int n = 0; n < 8; ++n) {
            float p0 = __expf(s[n][0] - mrun[0]);
            float p1 = __expf(s[n][1] - mrun[0]);
            float p2 = __expf(s[n][2] - mrun[1]);
            float p3 = __expf(s[n][3] - mrun[1]);
            lsum[0] += p0 + p1;
            lsum[1] += p2 + p3;
            pf[n][0] = h2bits(__floats2half2_rn(p0, p1));
            pf[n][1] = h2bits(__floats2half2_rn(p2, p3));
        }
#pragma unroll
        for (int half = 0; half < 2; ++half) {
            lsum[half] += __shfl_xor_sync(0xffffffffu, lsum[half], 1);
            lsum[half] += __shfl_xor_sync(0xffffffffu, lsum[half], 2);
            lrun[half] += lsum[half];
        }

        // ---- O += P V (P from regs; V B-frag via ldmatrix.x2.trans) ----
#pragma unroll
        for (int ks = 0; ks < 4; ++ks) {
            uint32_t af[4];
            af[0] = pf[2*ks][0];
            af[1] = pf[2*ks][1];
            af[2] = pf[2*ks+1][0];
            af[3] = pf[2*ks+1][1];
            uint32_t vrow = vbuf + ((uint32_t)(ks * 16 + (lane & 15))) * 272;
#pragma unroll
            for (int dt = 0; dt < 16; ++dt) {
                uint32_t r0, r1;
                asm volatile(
                    "ldmatrix.sync.aligned.m8n8.x2.trans.shared.b16 {%0,%1}, [%2];"
                    : "=r"(r0), "=r"(r1) : "r"(vrow + dt * 16));
                mma16(o[dt], af, r0, r1);
            }
        }
    }

    // ---- finalize ----
    float inv0 = 1.f / lrun[0];
    float inv1 = 1.f / lrun[1];
#pragma unroll
    for (int dt = 0; dt < 16; ++dt) {
        int row = m0 + w * 16 + lg;
        int col = dt * 8 + 2 * lc;
        *(__half2*)&Oh[((size_t)row * NUM_HEADS + h) * HEAD_DIM + col] =
            __floats2half2_rn(o[dt][0] * inv0, o[dt][1] * inv0);
        *(__half2*)&Oh[((size_t)(row + 8) * NUM_HEADS + h) * HEAD_DIM + col] =
            __floats2half2_rn(o[dt][2] * inv1, o[dt][3] * inv1);
    }
}

// =================================================================
// kernel_launch
// =================================================================
extern "C" void kernel_launch(void* const* d_in, const int* in_sizes, int n_in,
                              void* d_out, int out_size)
{
    const float* x   = (const float*)d_in[0];
    const int*   pos = (const int*)  d_in[1];
    const float* Wq  = (const float*)d_in[2];
    const float* Wk  = (const float*)d_in[3];
    const float* Wv  = (const float*)d_in[4];
    const float* Wo  = (const float*)d_in[5];
    const float* qsc = (const float*)d_in[6];
    const float* ksc = (const float*)d_in[7];
    float* out = (float*)d_out;

    float *gq, *gk;
    __half *gqh, *gkh, *gvh, *gctxh, *gxh, *gwqkvT, *gwoT;
    cudaGetSymbolAddress((void**)&gq,     g_q);
    cudaGetSymbolAddress((void**)&gk,     g_k);
    cudaGetSymbolAddress((void**)&gqh,    g_qh);
    cudaGetSymbolAddress((void**)&gkh,    g_kh);
    cudaGetSymbolAddress((void**)&gvh,    g_vh);
    cudaGetSymbolAddress((void**)&gctxh,  g_ctxh);
    cudaGetSymbolAddress((void**)&gxh,    g_xh);
    cudaGetSymbolAddress((void**)&gwqkvT, g_wqkvT);
    cudaGetSymbolAddress((void**)&gwoT,   g_woT);

    const int NQ = NUM_HEADS * HEAD_DIM;   // 4096
    const int NK = NUM_KV * HEAD_DIM;      // 1024

    cudaFuncSetAttribute(gemm_f16,
                         cudaFuncAttributeMaxDynamicSharedMemorySize, GEMM_SMEM);
    cudaFuncSetAttribute(flash_f16_kernel,
                         cudaFuncAttributeMaxDynamicSharedMemorySize, FLASH_SMEM);

    // ---- pre-pass: x -> fp16; weights -> fp16 transposed ----
    to_half_kernel<<<1024, 256>>>(x, gxh, (SEQ * D_IN) / 4);
    transpose_half_kernel<<<dim3(NQ / 32, D_IN / 32), 256>>>(Wq, gwqkvT, D_IN, NQ);
    transpose_half_kernel<<<dim3(NK / 32, D_IN / 32), 256>>>(
        Wk, gwqkvT + (size_t)NQ * D_IN, D_IN, NK);
    transpose_half_kernel<<<dim3(NK / 32, D_IN / 32), 256>>>(
        Wv, gwqkvT + (size_t)(NQ + NK) * D_IN, D_IN, NK);
    transpose_half_kernel<<<dim3(D_IN / 32, NQ / 32), 256>>>(Wo, gwoT, NQ, D_IN);

    // ---- fused QKV projection (N = 6144) ----
    gemm_f16<<<dim3(6144 / 128, SEQ / 128), 256, GEMM_SMEM>>>(
        gxh, gwqkvT, gq, gk, gvh, NQ, NQ, NQ + NK, 6144, D_IN);

    // ---- RMSNorm + RoPE ----
    norm_rope_kernel<<<SEQ, 128>>>(gq, gk, gqh, gkh, qsc, ksc, pos);

    // ---- Flash attention ----
    flash_f16_kernel<<<dim3(SEQ / 128, NUM_HEADS), 256, FLASH_SMEM>>>(
        gqh, gkh, gvh, gctxh);

    // ---- Output projection (always region 0) ----
    gemm_f16<<<dim3(D_IN / 128, SEQ / 128), 256, GEMM_SMEM>>>(
        gctxh, gwoT, out, nullptr, nullptr, D_IN, D_IN, D_IN, D_IN, NQ);
}

// round 7
// speedup vs baseline: 8.0996x; 1.0126x over previous
#include <cuda_runtime.h>
#include <cuda_fp16.h>
#include <math.h>
#include <stdint.h>

#define D_IN       4096
#define NUM_HEADS  32
#define HEAD_DIM   128
#define NUM_KV     8
#define SEQ        2048

// -------- scratch (device globals; no allocation allowed) --------
__device__ __half g_qh [(size_t)SEQ * NUM_HEADS * HEAD_DIM];
__device__ __half g_kh [(size_t)SEQ * NUM_KV   * HEAD_DIM];
__device__ __half g_vh [(size_t)SEQ * NUM_KV   * HEAD_DIM];
__device__ __half g_ctxh[(size_t)SEQ * NUM_HEADS * HEAD_DIM];
__device__ __half g_xh [(size_t)SEQ * D_IN];
__device__ __half g_wqkvT[(size_t)6144 * D_IN];                 // [Wq^T|Wk^T|Wv^T]
__device__ __half g_woT[(size_t)D_IN * (NUM_HEADS*HEAD_DIM)];
__device__ float  g_rope[(size_t)SEQ * 64 * 2];                 // [tok][f]{cos,sin}

// ---------------- helpers ----------------
__device__ __forceinline__ uint32_t smem_u32(const void* p) {
    uint32_t a;
    asm("{ .reg .u64 t; cvta.to.shared.u64 t, %1; cvt.u32.u64 %0, t; }"
        : "=r"(a) : "l"(p));
    return a;
}
__device__ __forceinline__ void cp16(uint32_t d, const void* s) {
    asm volatile("cp.async.cg.shared.global [%0], [%1], 16;"
                 :: "r"(d), "l"(s) : "memory");
}
#define CP_COMMIT() asm volatile("cp.async.commit_group;" ::: "memory")
#define CP_WAIT1()  asm volatile("cp.async.wait_group 1;" ::: "memory")

__device__ __forceinline__ void mma16(float* c, const uint32_t* a,
                                      uint32_t b0, uint32_t b1) {
    asm volatile(
        "mma.sync.aligned.m16n8k16.row.col.f32.f16.f16.f32 "
        "{%0,%1,%2,%3},{%4,%5,%6,%7},{%8,%9},{%0,%1,%2,%3};\n"
        : "+f"(c[0]), "+f"(c[1]), "+f"(c[2]), "+f"(c[3])
        : "r"(a[0]), "r"(a[1]), "r"(a[2]), "r"(a[3]), "r"(b0), "r"(b1));
}
__device__ __forceinline__ void ldsm4(uint32_t addr, uint32_t& r0, uint32_t& r1,
                                      uint32_t& r2, uint32_t& r3) {
    asm volatile("ldmatrix.sync.aligned.m8n8.x4.shared.b16 {%0,%1,%2,%3}, [%4];"
                 : "=r"(r0), "=r"(r1), "=r"(r2), "=r"(r3) : "r"(addr));
}
__device__ __forceinline__ uint32_t h2bits(__half2 h) {
    return *(uint32_t*)&h;
}

// =================================================================
// fp16 GEMM. MODE 0: plain fp32 out (ld = N).
// MODE 1: fused QKV epilogue:
//   cols [0,4096)     -> RMSNorm+RoPE -> Qout fp16
//   cols [4096,5120)  -> RMSNorm+RoPE -> Kout fp16
//   cols [5120,6144)  -> Vout fp16
// BM=BN=128, BK=64, 256 thr, 3-stage cp.async, ldmatrix frags.
// =================================================================
#define GSTAGE_BYTES 36864
#define GEMM_SMEM (3 * GSTAGE_BYTES)

template<int MODE>
__global__ __launch_bounds__(256, 2) void gemm_f16(
    const __half* __restrict__ A, const __half* __restrict__ B,
    float* __restrict__ Cout,
    __half* __restrict__ Qout, __half* __restrict__ Kout, __half* __restrict__ Vout,
    const float* __restrict__ qsc, const float* __restrict__ ksc,
    const float* __restrict__ ropeT,
    int N, int K)
{
    extern __shared__ __half sh[];
    const uint32_t sb = smem_u32(sh);
    const int tid = threadIdx.x;
    const int lane = tid & 31, wid = tid >> 5;
    const int wm = wid & 3, wn = wid >> 2;
    const int lg = lane >> 2, lc = lane & 3;
    const int m0 = blockIdx.y * 128, n0 = blockIdx.x * 128;
    const int nsteps = K / 64;
    const int lrow = tid >> 3;
    const int lchk = tid & 7;

    const uint32_t a_off = (uint32_t)((wm * 32 + (lane & 15)) * 144 + (lane >> 4) * 16);
    const uint32_t b_off = (uint32_t)(18432 +
        (wn * 64 + (lane & 7) + ((lane >> 4) * 8)) * 144 + ((lane >> 3) & 1) * 16);

    float acc[2][8][4];
#pragma unroll
    for (int i = 0; i < 2; ++i)
#pragma unroll
        for (int j = 0; j < 8; ++j)
#pragma unroll
            for (int e = 0; e < 4; ++e) acc[i][j][e] = 0.f;

    const __half* Ag = A + (size_t)m0 * K;
    const __half* Bg = B + (size_t)n0 * K;

#define LOAD_STAGE(s, k0) do {                                            \
    uint32_t as_ = sb + (uint32_t)(s) * GSTAGE_BYTES;                     \
    uint32_t bs_ = as_ + 18432;                                           \
    _Pragma("unroll")                                                     \
    for (int j_ = 0; j_ < 4; ++j_) {                                      \
        int row_ = lrow + 32 * j_;                                        \
        cp16(as_ + row_ * 144 + lchk * 16,                                \
             Ag + (size_t)row_ * K + (k0) + lchk * 8);                    \
        cp16(bs_ + row_ * 144 + lchk * 16,                                \
             Bg + (size_t)row_ * K + (k0) + lchk * 8);                    \
    }                                                                     \
} while (0)

    LOAD_STAGE(0, 0);  CP_COMMIT();
    LOAD_STAGE(1, 64); CP_COMMIT();

    for (int s = 0; s < nsteps; ++s) {
        CP_WAIT1();
        __syncthreads();
        if (s + 2 < nsteps) {
            int sn = s + 2; int bufn = sn - (sn / 3) * 3;
            LOAD_STAGE(bufn, sn * 64);
        }
        CP_COMMIT();

        const int buf = s - (s / 3) * 3;
        const uint32_t st = sb + (uint32_t)buf * GSTAGE_BYTES;
#pragma unroll
        for (int ks = 0; ks < 4; ++ks) {
            uint32_t af[2][4];
            ldsm4(st + a_off + ks * 32,            af[0][0], af[0][1], af[0][2], af[0][3]);
            ldsm4(st + a_off + ks * 32 + 16 * 144, af[1][0], af[1][1], af[1][2], af[1][3]);
            uint32_t bf[8][2];
#pragma unroll
            for (int ntp = 0; ntp < 4; ++ntp) {
                uint32_t r0, r1, r2, r3;
                ldsm4(st + b_off + ks * 32 + ntp * 16 * 144, r0, r1, r2, r3);
                bf[2*ntp][0] = r0; bf[2*ntp][1] = r1;
                bf[2*ntp+1][0] = r2; bf[2*ntp+1][1] = r3;
            }
#pragma unroll
            for (int nt = 0; nt < 8; ++nt) {
                mma16(acc[0][nt], af[0], bf[nt][0], bf[nt][1]);
                mma16(acc[1][nt], af[1], bf[nt][0], bf[nt][1]);
            }
        }
    }
#undef LOAD_STAGE

    if (MODE == 0) {
#pragma unroll
        for (int mt = 0; mt < 2; ++mt)
#pragma unroll
            for (int nt = 0; nt < 8; ++nt) {
                int row = m0 + wm * 32 + mt * 16 + lg;
                int col = n0 + wn * 64 + nt * 8 + 2 * lc;
                *(float2*)&Cout[(size_t)row * N + col] =
                    make_float2(acc[mt][nt][0], acc[mt][nt][1]);
                *(float2*)&Cout[(size_t)(row + 8) * N + col] =
                    make_float2(acc[mt][nt][2], acc[mt][nt][3]);
            }
        return;
    }

    // ---------------- MODE 1: fused QKV epilogue ----------------
    if (n0 >= 5120) {
        // V region: plain fp16
#pragma unroll
        for (int mt = 0; mt < 2; ++mt)
#pragma unroll
            for (int nt = 0; nt < 8; ++nt) {
                int row = m0 + wm * 32 + mt * 16 + lg;
                int col = n0 - 5120 + wn * 64 + nt * 8 + 2 * lc;
                *(__half2*)&Vout[(size_t)row * 1024 + col] =
                    __floats2half2_rn(acc[mt][nt][0], acc[mt][nt][1]);
                *(__half2*)&Vout[(size_t)(row + 8) * 1024 + col] =
                    __floats2half2_rn(acc[mt][nt][2], acc[mt][nt][3]);
            }
        return;
    }

    // Q or K region: RMSNorm + RoPE
    const bool isQ = (n0 < 4096);
    const float* sc = isQ ? qsc : ksc;
    float* ssb = (float*)sh;          // [2][128]
    float* epi = (float*)sh + 256;    // [128][132]

    __syncthreads();  // all smem pipeline reads done; safe to overwrite

    // per-row sum of squares (shfl over lc, then cross-wn via smem)
#pragma unroll
    for (int mt = 0; mt < 2; ++mt) {
        float s0 = 0.f, s1 = 0.f;
#pragma unroll
        for (int nt = 0; nt < 8; ++nt) {
            s0 += acc[mt][nt][0]*acc[mt][nt][0] + acc[mt][nt][1]*acc[mt][nt][1];
            s1 += acc[mt][nt][2]*acc[mt][nt][2] + acc[mt][nt][3]*acc[mt][nt][3];
        }
        s0 += __shfl_xor_sync(0xffffffffu, s0, 1);
        s0 += __shfl_xor_sync(0xffffffffu, s0, 2);
        s1 += __shfl_xor_sync(0xffffffffu, s1, 1);
        s1 += __shfl_xor_sync(0xffffffffu, s1, 2);
        if (lc == 0) {
            int r = wm * 32 + mt * 16 + lg;
            ssb[wn * 128 + r]     = s0;
            ssb[wn * 128 + r + 8] = s1;
        }
    }
    __syncthreads();

    // normalize + scale, stage to smem
#pragma unroll
    for (int mt = 0; mt < 2; ++mt) {
        int r0 = wm * 32 + mt * 16 + lg;
        float rs0 = rsqrtf((ssb[r0]     + ssb[128 + r0])     * (1.f/128.f) + 1e-6f);
        float rs1 = rsqrtf((ssb[r0 + 8] + ssb[128 + r0 + 8]) * (1.f/128.f) + 1e-6f);
#pragma unroll
        for (int nt = 0; nt < 8; ++nt) {
            int c0 = wn * 64 + nt * 8 + 2 * lc;
            float2 scv = *(const float2*)&sc[c0];
            *(float2*)&epi[r0 * 132 + c0] =
                make_float2(acc[mt][nt][0] * rs0 * scv.x, acc[mt][nt][1] * rs0 * scv.y);
            *(float2*)&epi[(r0 + 8) * 132 + c0] =
                make_float2(acc[mt][nt][2] * rs1 * scv.x, acc[mt][nt][3] * rs1 * scv.y);
        }
    }
    __syncthreads();

    // rope + fp16 write
    const int head = isQ ? (n0 >> 7) : ((n0 - 4096) >> 7);
    const int hstride = isQ ? NUM_HEADS : NUM_KV;
    __half* outp = isQ ? Qout : Kout;
#pragma unroll
    for (int mt = 0; mt < 2; ++mt) {
#pragma unroll
        for (int nt = 0; nt < 8; ++nt) {
            int r0 = wm * 32 + mt * 16 + lg;
            int c0 = wn * 64 + nt * 8 + 2 * lc;
            int cf = c0 & 63;
            float sgn = (c0 < 64) ? -1.f : 1.f;
#pragma unroll
            for (int hr = 0; hr < 2; ++hr) {
                int r = r0 + hr * 8;
                int tok = m0 + r;
                float4 tb = *(const float4*)&ropeT[(size_t)(tok * 64 + cf) * 2];
                float2 v = *(const float2*)&epi[r * 132 + c0];
                float2 p = *(const float2*)&epi[r * 132 + (c0 ^ 64)];
                float o0 = fmaf(v.x, tb.x, sgn * p.x * tb.y);
                float o1 = fmaf(v.y, tb.z, sgn * p.y * tb.w);
                *(__half2*)&outp[((size_t)tok * hstride + head) * 128 + c0] =
                    __floats2half2_rn(o0, o1);
            }
        }
    }
}

// =================================================================
// pre-pass kernels
// =================================================================
__global__ __launch_bounds__(256) void to_half_kernel(
    const float* __restrict__ in, __half* __restrict__ out, int n4)
{
    int i = blockIdx.x * blockDim.x + threadIdx.x;
    int stride = gridDim.x * blockDim.x;
    for (; i < n4; i += stride) {
        float4 v = ((const float4*)in)[i];
        __half2 h0 = __floats2half2_rn(v.x, v.y);
        __half2 h1 = __floats2half2_rn(v.z, v.w);
        ((uint2*)out)[i] = make_uint2(h2bits(h0), h2bits(h1));
    }
}

// rope table: [tok][f] -> {cos, sin}, double-precision angle
__global__ __launch_bounds__(256) void rope_table_kernel(
    const int* __restrict__ positions, float* __restrict__ tbl)
{
    int idx = blockIdx.x * 256 + threadIdx.x;   // 0 .. SEQ*64-1
    int tok = idx >> 6, f = idx & 63;
    double invf = exp2(-(double)f * (13.287712379549449 / 64.0));
    double ang  = (double)positions[tok] * invf;
    const double twopi = 6.283185307179586476925287;
    ang -= twopi * floor(ang / twopi);
    float c, s;
    sincosf((float)ang, &s, &c);
    tbl[(size_t)idx * 2]     = c;
    tbl[(size_t)idx * 2 + 1] = s;
}

// W [K][N] fp32 -> WT [N][K] fp16. 64x64 tiles, stride-65 staging.
__global__ __launch_bounds__(256) void transpose_half_v2(
    const float* __restrict__ W, __half* __restrict__ WT, int K, int N)
{
    __shared__ float s[64][65];
    const int tid = threadIdx.x;
    const int k0 = blockIdx.y * 64;
    const int n0 = blockIdx.x * 64;
    const int rk = tid >> 4;     // 0..15
    const int cn = tid & 15;     // 0..15
#pragma unroll
    for (int it = 0; it < 4; ++it) {
        int k = rk + it * 16;
        float4 v = *(const float4*)&W[(size_t)(k0 + k) * N + n0 + cn * 4];
        s[k][cn*4+0] = v.x; s[k][cn*4+1] = v.y;
        s[k][cn*4+2] = v.z; s[k][cn*4+3] = v.w;
    }
    __syncthreads();
    const int rn = tid >> 3;     // 0..31
    const int ck = tid & 7;      // 0..7
#pragma unroll
    for (int it = 0; it < 2; ++it) {
        int n = rn + it * 32;
        __half h[8];
#pragma unroll
        for (int i = 0; i < 8; ++i) h[i] = __float2half_rn(s[ck*8+i][n]);
        *(uint4*)&WT[(size_t)(n0 + n) * K + k0 + ck * 8] = *(uint4*)h;
    }
}

// =================================================================
// Flash attention fp16, BM=128, BN=64, 256 threads.
// cp.async double-buffered K/V; Q/K frags via ldmatrix.x4;
// P kept in registers.
// =================================================================
#define FST 136
#define FO_Q  0
#define FO_K0 17408
#define FO_K1 26112
#define FO_V0 34816
#define FO_V1 43520
#define FLASH_SMEM (52224 * 2)

__global__ __launch_bounds__(256, 1) void flash_f16_kernel(
    const __half* __restrict__ Qh, const __half* __restrict__ Kh,
    const __half* __restrict__ Vh, __half* __restrict__ Oh)
{
    extern __shared__ __half fsm[];
    const uint32_t sb = smem_u32(fsm);
    __half* Qs = fsm + FO_Q;

    const int tid  = threadIdx.x;
    const int lane = tid & 31;
    const int w    = tid >> 5;
    const int lg   = lane >> 2;
    const int lc   = lane & 3;
    const int h    = blockIdx.y;
    const int kvh  = h >> 2;
    const int qt   = gridDim.x - 1 - blockIdx.x;
    const int m0   = qt * 128;
    const int ntmax = 2 * qt + 1;
    const float softscale = 0.08838834764831845f;

    const int ctok = tid >> 4;
    const int cu   = tid & 15;

    const int m_sel = lane >> 3;
    const int r_sel = lane & 7;
    const uint32_t q_lane = sb + (uint32_t)((w * 16 + (m_sel & 1) * 8 + r_sel) * 272
                                            + (m_sel >> 1) * 16);
    const uint32_t k_lane_off = (uint32_t)(((m_sel >> 1) * 8 + r_sel) * 272
                                           + (m_sel & 1) * 16);

    {
        uint32_t kd = sb + FO_K0 * 2;
        uint32_t vd = sb + FO_V0 * 2;
#pragma unroll
        for (int it = 0; it < 4; ++it) {
            int tok = ctok + it * 16;
            cp16(kd + tok * 272 + cu * 16,
                 Kh + ((size_t)tok * NUM_KV + kvh) * HEAD_DIM + cu * 8);
            cp16(vd + tok * 272 + cu * 16,
                 Vh + ((size_t)tok * NUM_KV + kvh) * HEAD_DIM + cu * 8);
        }
        CP_COMMIT();
    }

#pragma unroll
    for (int it = 0; it < 8; ++it) {
        int id  = tid + it * 256;
        int tok = id >> 4;
        int u   = id & 15;
        *(uint4*)&Qs[tok * FST + u * 8] =
            *(const uint4*)&Qh[((size_t)(m0 + tok) * NUM_HEADS + h) * HEAD_DIM + u * 8];
    }

    float o[16][4];
#pragma unroll
    for (int dt = 0; dt < 16; ++dt)
#pragma unroll
        for (int e = 0; e < 4; ++e) o[dt][e] = 0.f;
    float mrun[2] = {-1e30f, -1e30f};
    float lrun[2] = {0.f, 0.f};

    for (int nt = 0; nt <= ntmax; ++nt) {
        const int n0 = nt * 64;
        const uint32_t kbuf = sb + (((nt & 1) ? FO_K1 : FO_K0)) * 2;
        const uint32_t vbuf = sb + (((nt & 1) ? FO_V1 : FO_V0)) * 2;

        __syncthreads();
        if (nt + 1 <= ntmax) {
            const int pn0 = (nt + 1) * 64;
            uint32_t kd = sb + ((((nt + 1) & 1) ? FO_K1 : FO_K0)) * 2;
            uint32_t vd = sb + ((((nt + 1) & 1) ? FO_V1 : FO_V0)) * 2;
#pragma unroll
            for (int it = 0; it < 4; ++it) {
                int tok = ctok + it * 16;
                cp16(kd + tok * 272 + cu * 16,
                     Kh + ((size_t)(pn0 + tok) * NUM_KV + kvh) * HEAD_DIM + cu * 8);
                cp16(vd + tok * 272 + cu * 16,
                     Vh + ((size_t)(pn0 + tok) * NUM_KV + kvh) * HEAD_DIM + cu * 8);
            }
        }
        CP_COMMIT();
        CP_WAIT1();
        __syncthreads();

        float s[8][4];
#pragma unroll
        for (int n = 0; n < 8; ++n)
#pragma unroll
            for (int e = 0; e < 4; ++e) s[n][e] = 0.f;

        const uint32_t k_lane = kbuf + k_lane_off;
#pragma unroll
        for (int ks = 0; ks < 8; ++ks) {
            uint32_t af[4];
            ldsm4(q_lane + ks * 32, af[0], af[1], af[2], af[3]);
#pragma unroll
            for (int np = 0; np < 4; ++np) {
                uint32_t r0, r1, r2, r3;
                ldsm4(k_lane + np * 16 * 272 + ks * 32, r0, r1, r2, r3);
                mma16(s[2*np],   af, r0, r1);
                mma16(s[2*np+1], af, r2, r3);
            }
        }

        const bool diag = (nt >= 2 * qt);
        float pmax[2] = {-1e30f, -1e30f};
#pragma unroll
        for (int n = 0; n < 8; ++n) {
#pragma unroll
            for (int e = 0; e < 4; ++e) {
                float v = s[n][e] * softscale;
                if (diag) {
                    int row = m0 + w * 16 + lg + (e >> 1) * 8;
                    int col = n0 + n * 8 + 2 * lc + (e & 1);
                    if (col > row) v = -1e30f;
                }
                s[n][e] = v;
                pmax[e >> 1] = fmaxf(pmax[e >> 1], v);
            }
        }
#pragma unroll
        for (int half = 0; half < 2; ++half) {
            pmax[half] = fmaxf(pmax[half], __shfl_xor_sync(0xffffffffu, pmax[half], 1));
            pmax[half] = fmaxf(pmax[half], __shfl_xor_sync(0xffffffffu, pmax[half], 2));
        }
        float alpha[2];
#pragma unroll
        for (int half = 0; half < 2; ++half) {
            float nm = fmaxf(mrun[half], pmax[half]);
            alpha[half] = __expf(mrun[half] - nm);
            mrun[half] = nm;
            lrun[half] *= alpha[half];
        }
#pragma unroll
        for (int dt = 0; dt < 16; ++dt) {
            o[dt][0] *= alpha[0]; o[dt][1] *= alpha[0];
            o[dt][2] *= alpha[1]; o[dt][3] *= alpha[1];
        }
        uint32_t pf[8][2];
        float lsum[2] = {0.f, 0.f};
#pragma unroll
        for (int n = 0; n < 8; ++n) {
            float p0 = __expf(s[n][0] - mrun[0]);
            float p1 = __expf(s[n][1] - mrun[0]);
            float p2 = __expf(s[n][2] - mrun[1]);
            float p3 = __expf(s[n][3] - mrun[1]);
            lsum[0] += p0 + p1;
            lsum[1] += p2 + p3;
            pf[n][0] = h2bits(__floats2half2_rn(p0, p1));
            pf[n][1] = h2bits(__floats2half2_rn(p2, p3));
        }
#pragma unroll
        for (int half = 0; half < 2; ++half) {
            lsum[half] += __shfl_xor_sync(0xffffffffu, lsum[half], 1);
            lsum[half] += __shfl_xor_sync(0xffffffffu, lsum[half], 2);
            lrun[half] += lsum[half];
        }

#pragma unroll
        for (int ks = 0; ks < 4; ++ks) {
            uint32_t af[4];
            af[0] = pf[2*ks][0];
            af[1] = pf[2*ks][1];
            af[2] = pf[2*ks+1][0];
            af[3] = pf[2*ks+1][1];
            uint32_t vrow = vbuf + ((uint32_t)(ks * 16 + (lane & 15))) * 272;
#pragma unroll
            for (int dt = 0; dt < 16; ++dt) {
                uint32_t r0, r1;
                asm volatile(
                    "ldmatrix.sync.aligned.m8n8.x2.trans.shared.b16 {%0,%1}, [%2];"
                    : "=r"(r0), "=r"(r1) : "r"(vrow + dt * 16));
                mma16(o[dt], af, r0, r1);
            }
        }
    }

    float inv0 = 1.f / lrun[0];
    float inv1 = 1.f / lrun[1];
#pragma unroll
    for (int dt = 0; dt < 16; ++dt) {
        int row = m0 + w * 16 + lg;
        int col = dt * 8 + 2 * lc;
        *(__half2*)&Oh[((size_t)row * NUM_HEADS + h) * HEAD_DIM + col] =
            __floats2half2_rn(o[dt][0] * inv0, o[dt][1] * inv0);
        *(__half2*)&Oh[((size_t)(row + 8) * NUM_HEADS + h) * HEAD_DIM + col] =
            __floats2half2_rn(o[dt][2] * inv1, o[dt][3] * inv1);
    }
}

// =================================================================
// kernel_launch
// =================================================================
extern "C" void kernel_launch(void* const* d_in, const int* in_sizes, int n_in,
                              void* d_out, int out_size)
{
    const float* x   = (const float*)d_in[0];
    const int*   pos = (const int*)  d_in[1];
    const float* Wq  = (const float*)d_in[2];
    const float* Wk  = (const float*)d_in[3];
    const float* Wv  = (const float*)d_in[4];
    const float* Wo  = (const float*)d_in[5];
    const float* qsc = (const float*)d_in[6];
    const float* ksc = (const float*)d_in[7];
    float* out = (float*)d_out;

    __half *gqh, *gkh, *gvh, *gctxh, *gxh, *gwqkvT, *gwoT;
    float* grope;
    cudaGetSymbolAddress((void**)&gqh,    g_qh);
    cudaGetSymbolAddress((void**)&gkh,    g_kh);
    cudaGetSymbolAddress((void**)&gvh,    g_vh);
    cudaGetSymbolAddress((void**)&gctxh,  g_ctxh);
    cudaGetSymbolAddress((void**)&gxh,    g_xh);
    cudaGetSymbolAddress((void**)&gwqkvT, g_wqkvT);
    cudaGetSymbolAddress((void**)&gwoT,   g_woT);
    cudaGetSymbolAddress((void**)&grope,  g_rope);

    const int NQ = NUM_HEADS * HEAD_DIM;   // 4096
    const int NK = NUM_KV * HEAD_DIM;      // 1024

    cudaFuncSetAttribute(gemm_f16<0>,
                         cudaFuncAttributeMaxDynamicSharedMemorySize, GEMM_SMEM);
    cudaFuncSetAttribute(gemm_f16<1>,
                         cudaFuncAttributeMaxDynamicSharedMemorySize, GEMM_SMEM);
    cudaFuncSetAttribute(flash_f16_kernel,
                         cudaFuncAttributeMaxDynamicSharedMemorySize, FLASH_SMEM);

    // ---- pre-pass ----
    to_half_kernel<<<1024, 256>>>(x, gxh, (SEQ * D_IN) / 4);
    rope_table_kernel<<<(SEQ * 64) / 256, 256>>>(pos, grope);
    transpose_half_v2<<<dim3(NQ / 64, D_IN / 64), 256>>>(Wq, gwqkvT, D_IN, NQ);
    transpose_half_v2<<<dim3(NK / 64, D_IN / 64), 256>>>(
        Wk, gwqkvT + (size_t)NQ * D_IN, D_IN, NK);
    transpose_half_v2<<<dim3(NK / 64, D_IN / 64), 256>>>(
        Wv, gwqkvT + (size_t)(NQ + NK) * D_IN, D_IN, NK);
    transpose_half_v2<<<dim3(D_IN / 64, NQ / 64), 256>>>(Wo, gwoT, NQ, D_IN);

    // ---- fused QKV projection + RMSNorm + RoPE ----
    gemm_f16<1><<<dim3(6144 / 128, SEQ / 128), 256, GEMM_SMEM>>>(
        gxh, gwqkvT, nullptr, gqh, gkh, gvh, qsc, ksc, grope, 6144, D_IN);

    // ---- Flash attention ----
    flash_f16_kernel<<<dim3(SEQ / 128, NUM_HEADS), 256, FLASH_SMEM>>>(
        gqh, gkh, gvh, gctxh);

    // ---- Output projection ----
    gemm_f16<0><<<dim3(D_IN / 128, SEQ / 128), 256, GEMM_SMEM>>>(
        gctxh, gwoT, out, nullptr, nullptr, nullptr, nullptr, nullptr, nullptr,
        D_IN, NQ);
}